// round 2
// baseline (speedup 1.0000x reference)
#include <cuda_runtime.h>
#include <math.h>

#define Bq   8
#define Lq   1024
#define Eq   1024
#define Hq   16
#define DKq  64
#define Mq   (Bq*Lq)
#define NEGV (-1000000000.0f)
#define SCALEV 0.125f

// ---------------- scratch (no cudaMalloc allowed) ----------------
__device__ float g_Q [Mq*Eq];
__device__ float g_K [Mq*Eq];
__device__ float g_V [Mq*Eq];
__device__ float g_Z [Mq*Eq];
__device__ float g_X1[Mq*Eq];
__device__ float g_X2[Mq*Eq];
__device__ float g_Hb[Mq*Eq];

// ---------------- generic 64x64x16 tiled fp32 GEMM ----------------
__global__ __launch_bounds__(256) void gemm64(
    const float* __restrict__ A, const float* __restrict__ W,
    float* __restrict__ C, const float* __restrict__ bias,
    const int* __restrict__ lens, int Kdim, int ldb, long bstride, int relu)
{
    __shared__ float As[16][64];
    __shared__ float Bs[16][64];
    const int tid = threadIdx.x;
    const int tx = tid & 15, ty = tid >> 4;
    const int m0 = blockIdx.x * 64;
    const int n0 = blockIdx.y * 64;
    const float* Bp = W + (long)blockIdx.y * bstride;
    const int arow = tid >> 2, aq = tid & 3;
    const int brow = tid >> 4, bq = tid & 15;

    float acc[4][4];
#pragma unroll
    for (int i = 0; i < 4; i++)
#pragma unroll
        for (int j = 0; j < 4; j++) acc[i][j] = 0.f;

    for (int k0 = 0; k0 < Kdim; k0 += 16) {
        float4 av = *(const float4*)(A + (long)(m0 + arow) * Kdim + k0 + aq * 4);
        As[aq*4+0][arow] = av.x;
        As[aq*4+1][arow] = av.y;
        As[aq*4+2][arow] = av.z;
        As[aq*4+3][arow] = av.w;
        *(float4*)(&Bs[brow][bq*4]) =
            *(const float4*)(Bp + (long)(k0 + brow) * ldb + bq * 4);
        __syncthreads();
#pragma unroll
        for (int kk = 0; kk < 16; kk++) {
            float4 a4 = *(const float4*)(&As[kk][ty*4]);
            float4 b4 = *(const float4*)(&Bs[kk][tx*4]);
            float aa[4] = {a4.x, a4.y, a4.z, a4.w};
            float bb[4] = {b4.x, b4.y, b4.z, b4.w};
#pragma unroll
            for (int i = 0; i < 4; i++)
#pragma unroll
                for (int j = 0; j < 4; j++)
                    acc[i][j] += aa[i] * bb[j];
        }
        __syncthreads();
    }

    float4 bv = make_float4(0.f, 0.f, 0.f, 0.f);
    if (bias) bv = *(const float4*)(bias + n0 + tx*4);
#pragma unroll
    for (int ii = 0; ii < 4; ii++) {
        int m = m0 + ty*4 + ii;
        int bidx = m >> 10, l = m & 1023;
        bool valid = l < lens[bidx];
        float4 r;
        r.x = acc[ii][0] + bv.x;
        r.y = acc[ii][1] + bv.y;
        r.z = acc[ii][2] + bv.z;
        r.w = acc[ii][3] + bv.w;
        if (relu) {
            r.x = fmaxf(r.x, 0.f); r.y = fmaxf(r.y, 0.f);
            r.z = fmaxf(r.z, 0.f); r.w = fmaxf(r.w, 0.f);
        }
        if (!valid) { r.x = 0.f; r.y = 0.f; r.z = 0.f; r.w = 0.f; }
        *(float4*)(C + (long)m * Eq + n0 + tx*4) = r;
    }
}

// ---------------- flash attention (Br=64, Bc=32, d=64) ----------------
__global__ __launch_bounds__(256) void flash_kernel(
    const float* __restrict__ Q, const float* __restrict__ K,
    const float* __restrict__ V, float* __restrict__ O,
    const int* __restrict__ lens, int causal)
{
    __shared__ float Qs[64][64];
    __shared__ float Ks[32][64];
    __shared__ float Vs[32][64];
    __shared__ float Ss[64][33];
    __shared__ float ms[64], ls[64], al[64];

    const int tid = threadIdx.x;
    const int tx = tid & 15, ty = tid >> 4;
    const int bh = blockIdx.y;
    const int b = bh >> 4, h = bh & 15;
    const int q0 = blockIdx.x * 64;
    const int len = lens[b];

    // FIXED: full 64x64 Q tile load (each thread loads 16 contiguous floats)
    {
        int r = tid >> 2;
        int c0 = (tid & 3) * 16;
        const float* qsrc = Q + ((long)(b*Lq + q0 + r))*Eq + h*DKq + c0;
#pragma unroll
        for (int p = 0; p < 4; p++)
            *(float4*)&Qs[r][c0 + p*4] = *(const float4*)(qsrc + p*4);
    }
    if (tid < 64) { ms[tid] = -INFINITY; ls[tid] = 0.f; }

    float o[4][4];
#pragma unroll
    for (int i = 0; i < 4; i++)
#pragma unroll
        for (int j = 0; j < 4; j++) o[i][j] = 0.f;

    const int kend = min(len, causal ? (q0 + 64) : Lq);
    __syncthreads();

    for (int k0 = 0; k0 < kend; k0 += 32) {
#pragma unroll
        for (int p = 0; p < 2; p++) {
            int r = (tid >> 4) + p*16, c = (tid & 15)*4;
            long gi = ((long)(b*Lq + k0 + r))*Eq + h*DKq + c;
            *(float4*)&Ks[r][c] = *(const float4*)(K + gi);
            *(float4*)&Vs[r][c] = *(const float4*)(V + gi);
        }
        __syncthreads();

        // S = Q K^T : per thread 4 rows x 2 cols
        float s[4][2] = {{0.f,0.f},{0.f,0.f},{0.f,0.f},{0.f,0.f}};
#pragma unroll
        for (int kk = 0; kk < 64; kk += 4) {
            float4 qv[4];
            qv[0] = *(const float4*)&Qs[ty*4+0][kk];
            qv[1] = *(const float4*)&Qs[ty*4+1][kk];
            qv[2] = *(const float4*)&Qs[ty*4+2][kk];
            qv[3] = *(const float4*)&Qs[ty*4+3][kk];
            float4 kv[2];
            kv[0] = *(const float4*)&Ks[tx*2+0][kk];
            kv[1] = *(const float4*)&Ks[tx*2+1][kk];
#pragma unroll
            for (int i = 0; i < 4; i++)
#pragma unroll
                for (int j = 0; j < 2; j++)
                    s[i][j] += qv[i].x*kv[j].x + qv[i].y*kv[j].y
                             + qv[i].z*kv[j].z + qv[i].w*kv[j].w;
        }
#pragma unroll
        for (int ii = 0; ii < 4; ii++) {
            int ig = q0 + ty*4 + ii;
#pragma unroll
            for (int jj = 0; jj < 2; jj++) {
                int jg = k0 + tx*2 + jj;
                float e = s[ii][jj];
                if (jg >= len) e += NEGV;
                if (causal && jg > ig) e += NEGV;
                Ss[ty*4+ii][tx*2+jj] = e * SCALEV;
            }
        }
        __syncthreads();

        // online softmax row pass
        if (tid < 64) {
            float mo = ms[tid];
            float mx = mo;
#pragma unroll 8
            for (int j = 0; j < 32; j++) mx = fmaxf(mx, Ss[tid][j]);
            float a = __expf(mo - mx);   // exp(-inf)=0 on first chunk
            float rs = 0.f;
#pragma unroll 8
            for (int j = 0; j < 32; j++) {
                float p = __expf(Ss[tid][j] - mx);
                Ss[tid][j] = p;
                rs += p;
            }
            ms[tid] = mx;
            ls[tid] = ls[tid]*a + rs;
            al[tid] = a;
        }
        __syncthreads();

        // O = O*alpha + P V : per thread 4 rows x 4 d-cols
        float a0 = al[ty*4+0], a1 = al[ty*4+1], a2 = al[ty*4+2], a3 = al[ty*4+3];
#pragma unroll
        for (int d = 0; d < 4; d++) {
            o[0][d] *= a0; o[1][d] *= a1; o[2][d] *= a2; o[3][d] *= a3;
        }
#pragma unroll 8
        for (int j = 0; j < 32; j++) {
            float4 v = *(const float4*)&Vs[j][tx*4];
            float p0 = Ss[ty*4+0][j], p1 = Ss[ty*4+1][j];
            float p2 = Ss[ty*4+2][j], p3 = Ss[ty*4+3][j];
            o[0][0] += p0*v.x; o[0][1] += p0*v.y; o[0][2] += p0*v.z; o[0][3] += p0*v.w;
            o[1][0] += p1*v.x; o[1][1] += p1*v.y; o[1][2] += p1*v.z; o[1][3] += p1*v.w;
            o[2][0] += p2*v.x; o[2][1] += p2*v.y; o[2][2] += p2*v.z; o[2][3] += p2*v.w;
            o[3][0] += p3*v.x; o[3][1] += p3*v.y; o[3][2] += p3*v.z; o[3][3] += p3*v.w;
        }
        __syncthreads();
    }

#pragma unroll
    for (int ii = 0; ii < 4; ii++) {
        int ig = q0 + ty*4 + ii;
        bool valid = ig < len;
        float inv = valid ? (1.f / ls[ty*4+ii]) : 0.f;
        float4 r;
        r.x = o[ii][0]*inv; r.y = o[ii][1]*inv;
        r.z = o[ii][2]*inv; r.w = o[ii][3]*inv;
        if (!valid) { r.x = 0.f; r.y = 0.f; r.z = 0.f; r.w = 0.f; }
        *(float4*)(O + ((long)(b*Lq + ig))*Eq + h*DKq + tx*4) = r;
    }
}

// ---------------- fused residual + layernorm (one block per row) ----------------
__global__ __launch_bounds__(256) void ln_kernel(
    const float* __restrict__ A, const float* __restrict__ Z,
    const float* __restrict__ g, const float* __restrict__ bb,
    float* __restrict__ out)
{
    __shared__ float sred[8], ssred[8];
    const int row = blockIdx.x, tid = threadIdx.x;
    const float4* a4 = (const float4*)(A + (long)row * Eq);
    const float4* z4 = (const float4*)(Z + (long)row * Eq);
    float4 av = a4[tid], zv = z4[tid];
    float4 t = make_float4(av.x+zv.x, av.y+zv.y, av.z+zv.z, av.w+zv.w);
    float s  = t.x + t.y + t.z + t.w;
    float ss = t.x*t.x + t.y*t.y + t.z*t.z + t.w*t.w;
#pragma unroll
    for (int o2 = 16; o2 > 0; o2 >>= 1) {
        s  += __shfl_xor_sync(0xffffffffu, s,  o2);
        ss += __shfl_xor_sync(0xffffffffu, ss, o2);
    }
    int wid = tid >> 5, lane = tid & 31;
    if (lane == 0) { sred[wid] = s; ssred[wid] = ss; }
    __syncthreads();
    if (tid < 8) {
        s = sred[tid]; ss = ssred[tid];
#pragma unroll
        for (int o2 = 4; o2 > 0; o2 >>= 1) {
            s  += __shfl_xor_sync(0xffu, s,  o2);
            ss += __shfl_xor_sync(0xffu, ss, o2);
        }
        if (tid == 0) { sred[0] = s; ssred[0] = ss; }
    }
    __syncthreads();
    const float mu  = sred[0] * (1.f / Eq);
    const float var = ssred[0] * (1.f / Eq) - mu * mu;
    const float rinv = rsqrtf(var + 1e-5f);
    float4 gv = ((const float4*)g)[tid];
    float4 bv = ((const float4*)bb)[tid];
    float4 r;
    r.x = (t.x - mu) * rinv * gv.x + bv.x;
    r.y = (t.y - mu) * rinv * gv.y + bv.y;
    r.z = (t.z - mu) * rinv * gv.z + bv.z;
    r.w = (t.w - mu) * rinv * gv.w + bv.w;
    ((float4*)(out + (long)row * Eq))[tid] = r;
}

// ---------------- launch ----------------
extern "C" void kernel_launch(void* const* d_in, const int* in_sizes, int n_in,
                              void* d_out, int out_size)
{
    const float* x    = (const float*)d_in[0];
    const float* ctx  = (const float*)d_in[1];
    const int*   lens = (const int*)  d_in[2];
    const float* Wq1  = (const float*)d_in[4];
    const float* Wk1  = (const float*)d_in[5];
    const float* Wv1  = (const float*)d_in[6];
    const float* Wq2  = (const float*)d_in[7];
    const float* Wk2  = (const float*)d_in[8];
    const float* Wv2  = (const float*)d_in[9];
    const float* ln1g = (const float*)d_in[10];
    const float* ln1b = (const float*)d_in[11];
    const float* ln2g = (const float*)d_in[12];
    const float* ln2b = (const float*)d_in[13];
    const float* ln3g = (const float*)d_in[14];
    const float* ln3b = (const float*)d_in[15];
    const float* fc1w = (const float*)d_in[16];
    const float* fc1b = (const float*)d_in[17];
    const float* fc2w = (const float*)d_in[18];
    const float* fc2b = (const float*)d_in[19];
    float* out = (float*)d_out;

    float *Qb, *Kb, *Vb, *Zb, *X1, *X2, *Hb;
    cudaGetSymbolAddress((void**)&Qb, g_Q);
    cudaGetSymbolAddress((void**)&Kb, g_K);
    cudaGetSymbolAddress((void**)&Vb, g_V);
    cudaGetSymbolAddress((void**)&Zb, g_Z);
    cudaGetSymbolAddress((void**)&X1, g_X1);
    cudaGetSymbolAddress((void**)&X2, g_X2);
    cudaGetSymbolAddress((void**)&Hb, g_Hb);

    dim3 gg(Mq/64, Eq/64);           // 128 x 16
    dim3 fg(Lq/64, Bq*Hq);           // 16 x 128
    const long PSTRIDE = (long)Eq * DKq;  // per-head weight stride

    // --- self attention ---
    gemm64<<<gg, 256>>>(x, Wq1, Qb, nullptr, lens, Eq, DKq, PSTRIDE, 0);
    gemm64<<<gg, 256>>>(x, Wk1, Kb, nullptr, lens, Eq, DKq, PSTRIDE, 0);
    gemm64<<<gg, 256>>>(x, Wv1, Vb, nullptr, lens, Eq, DKq, PSTRIDE, 0);
    flash_kernel<<<fg, 256>>>(Qb, Kb, Vb, Zb, lens, 1);
    ln_kernel<<<Mq, 256>>>(x, Zb, ln1g, ln1b, X1);

    // --- cross attention (Q,K from context; V from x1) ---
    gemm64<<<gg, 256>>>(ctx, Wq2, Qb, nullptr, lens, Eq, DKq, PSTRIDE, 0);
    gemm64<<<gg, 256>>>(ctx, Wk2, Kb, nullptr, lens, Eq, DKq, PSTRIDE, 0);
    gemm64<<<gg, 256>>>(X1,  Wv2, Vb, nullptr, lens, Eq, DKq, PSTRIDE, 0);
    flash_kernel<<<fg, 256>>>(Qb, Kb, Vb, Zb, lens, 0);
    ln_kernel<<<Mq, 256>>>(X1, Zb, ln2g, ln2b, X2);

    // --- FFN ---
    gemm64<<<gg, 256>>>(X2, fc1w, Hb, fc1b, lens, Eq, Eq, 64L, 1);
    gemm64<<<gg, 256>>>(Hb, fc2w, Zb, fc2b, lens, Eq, Eq, 64L, 0);
    ln_kernel<<<Mq, 256>>>(X2, Zb, ln3g, ln3b, out);
}

// round 5
// speedup vs baseline: 1.3664x; 1.3664x over previous
#include <cuda_runtime.h>
#include <math.h>
#include <stdint.h>

#define Bq   8
#define Lq   1024
#define Eq   1024
#define Hq   16
#define DKq  64
#define Mq   (Bq*Lq)
#define NEGV (-1000000000.0f)
#define SCALEV 0.125f

#define GK 1024
#define BKc 32
#define NIT (GK / BKc)

// ---------------- scratch (no cudaMalloc allowed) ----------------
__device__ float g_Q [Mq*Eq];
__device__ float g_K [Mq*Eq];
__device__ float g_V [Mq*Eq];
__device__ float g_Z [Mq*Eq];
__device__ float g_X1[Mq*Eq];
__device__ float g_X2[Mq*Eq];
__device__ float g_Hb[Mq*Eq];

__device__ __forceinline__ uint32_t f2tf32(float x) {
    uint32_t r; asm("cvt.rna.tf32.f32 %0, %1;" : "=r"(r) : "f"(x)); return r;
}

__device__ __forceinline__ void mma_tf32(float* c, const uint32_t* a,
                                         const uint32_t* b) {
    asm volatile(
        "mma.sync.aligned.m16n8k8.row.col.f32.tf32.tf32.f32 "
        "{%0,%1,%2,%3}, {%4,%5,%6,%7}, {%8,%9}, {%0,%1,%2,%3};"
        : "+f"(c[0]), "+f"(c[1]), "+f"(c[2]), "+f"(c[3])
        : "r"(a[0]), "r"(a[1]), "r"(a[2]), "r"(a[3]), "r"(b[0]), "r"(b[1]));
}

// ================= mma.sync tf32 GEMM, 128x128 tile, BK=32 =================
// C[m,n] = act( sum_k A[m,k]*W(k,n) + bias[n] ) * rowmask
// W(k,n) = W[(n>>GRPs)*bstride + k*ldb + (n & ((1<<GRPs)-1))]
//
// SMEM fragment-major layout:
//  A: blk = (m>>4)*4 + ks  (ks = k>>3), 32 blocks of 128 floats
//     AF[blk*128 + lane*4 + r], lane = (m&7)*4 + (k&3),
//     r = ((m&15)>=8 ? 1:0) + ((k&7)>=4 ? 2:0)
//  B: blk = (n>>3)*4 + ks, 64 blocks of 64 floats
//     BF[blk*64 + lane*2 + r], lane = (n&7)*4 + (k&3), r = ((k&7)>=4)
__global__ __launch_bounds__(256) void gemm_mma(
    const float* __restrict__ A, const float* __restrict__ W,
    float* __restrict__ C, const float* __restrict__ bias,
    const int* __restrict__ lens, int ldb, long bstride, int GRPs, int relu)
{
    extern __shared__ float sm[];
    // stage s: AF = sm + s*8192, BF = sm + s*8192 + 4096
    const int tid = threadIdx.x;
    const int wid = tid >> 5, lane = tid & 31;
    const int warpm = wid >> 2, warpn = wid & 3;
    const int m0 = blockIdx.x * 128;
    const int n0 = blockIdx.y * 128;
    const int grpmask = (1 << GRPs) - 1;

    float acc[4][4][4];
#pragma unroll
    for (int mi = 0; mi < 4; mi++)
#pragma unroll
        for (int ni = 0; ni < 4; ni++)
#pragma unroll
            for (int c = 0; c < 4; c++) acc[mi][ni][c] = 0.f;

    float4 lA[4], lB[4];

    // ---- global load of one stage into registers ----
    auto ldg_stage = [&](int k0) {
#pragma unroll
        for (int i = 0; i < 4; i++) {
            int idx = tid * 4 + i;              // 0..1023
            int m = idx >> 3, kq = idx & 7;     // k = kq*4 + c
            lA[i] = *(const float4*)(A + (long)(m0 + m) * GK + k0 + kq * 4);
        }
#pragma unroll
        for (int i = 0; i < 4; i++) {
            int idx = tid * 4 + i;
            int k = idx >> 5;                   // 0..31
            int n4 = (idx & 31) * 4;            // 0..124
            const float* wp = W + ((long)((n0 + n4) >> GRPs)) * bstride
                                + (long)(k0 + k) * ldb + ((n0 + n4) & grpmask);
            lB[i] = *(const float4*)wp;
        }
    };

    // ---- scatter registers into fragment-major smem ----
    auto sts_stage = [&](int s) {
        float* AF = sm + s * 8192;
        float* BF = AF + 4096;
#pragma unroll
        for (int i = 0; i < 4; i++) {
            int idx = tid * 4 + i;
            int m = idx >> 3, kq = idx & 7;
            int blk = (m >> 4) * 4 + (kq >> 1);
            int r = ((m & 15) >= 8 ? 1 : 0) + ((kq & 1) ? 2 : 0);
            uint32_t* p = (uint32_t*)(AF + blk * 128 + (m & 7) * 16 + r);
            p[0]  = f2tf32(lA[i].x);     // k-step: +1 lane = +4 floats
            p[4]  = f2tf32(lA[i].y);
            p[8]  = f2tf32(lA[i].z);
            p[12] = f2tf32(lA[i].w);
        }
#pragma unroll
        for (int i = 0; i < 4; i++) {
            int idx = tid * 4 + i;
            int k = idx >> 5;
            int n4 = (idx & 31) * 4;
            int blk = (n4 >> 3) * 4 + (k >> 3);
            int r = ((k & 7) >= 4) ? 1 : 0;
            int lbase = (n4 & 7) * 4 + (k & 3);
            uint32_t* p = (uint32_t*)(BF + blk * 64 + lbase * 2 + r);
            p[0]  = f2tf32(lB[i].x);     // n-step: +4 lanes = +8 floats
            p[8]  = f2tf32(lB[i].y);
            p[16] = f2tf32(lB[i].z);
            p[24] = f2tf32(lB[i].w);
        }
    };

    auto compute_stage = [&](int s) {
        const float* AF = sm + s * 8192;
        const float* BF = AF + 4096;
#pragma unroll
        for (int ks = 0; ks < 4; ks++) {
            uint32_t af[4][4];
            uint32_t bf[4][2];
#pragma unroll
            for (int mi = 0; mi < 4; mi++)
                *(uint4*)af[mi] = *(const uint4*)
                    (AF + (((warpm * 4 + mi) * 4 + ks) * 32 + lane) * 4);
#pragma unroll
            for (int ni = 0; ni < 4; ni++)
                *(uint2*)bf[ni] = *(const uint2*)
                    (BF + (((warpn * 4 + ni) * 4 + ks) * 32 + lane) * 2);
#pragma unroll
            for (int mi = 0; mi < 4; mi++)
#pragma unroll
                for (int ni = 0; ni < 4; ni++)
                    mma_tf32(acc[mi][ni], af[mi], bf[ni]);
        }
    };

    ldg_stage(0);
    sts_stage(0);
    __syncthreads();

    for (int it = 0; it < NIT; it++) {
        const int s = it & 1;
        if (it + 1 < NIT) ldg_stage((it + 1) * BKc);
        compute_stage(s);
        if (it + 1 < NIT) {
            __syncthreads();          // all warps done reading stage s^1
            sts_stage(s ^ 1);
            __syncthreads();
        }
    }

    // ---- epilogue ----
    const int g = lane >> 2, t2 = (lane & 3) * 2;
#pragma unroll
    for (int mi = 0; mi < 4; mi++) {
        int mA = m0 + warpm * 64 + mi * 16 + g;
        int mB = mA + 8;
        bool vA = (mA & 1023) < lens[mA >> 10];
        bool vB = (mB & 1023) < lens[mB >> 10];
#pragma unroll
        for (int ni = 0; ni < 4; ni++) {
            int nn = n0 + warpn * 32 + ni * 8 + t2;
            float bx = 0.f, by = 0.f;
            if (bias) { float2 bv = *(const float2*)(bias + nn); bx = bv.x; by = bv.y; }
            float2 rA, rB;
            rA.x = acc[mi][ni][0] + bx; rA.y = acc[mi][ni][1] + by;
            rB.x = acc[mi][ni][2] + bx; rB.y = acc[mi][ni][3] + by;
            if (relu) {
                rA.x = fmaxf(rA.x, 0.f); rA.y = fmaxf(rA.y, 0.f);
                rB.x = fmaxf(rB.x, 0.f); rB.y = fmaxf(rB.y, 0.f);
            }
            if (!vA) { rA.x = 0.f; rA.y = 0.f; }
            if (!vB) { rB.x = 0.f; rB.y = 0.f; }
            *(float2*)(C + (long)mA * Eq + nn) = rA;
            *(float2*)(C + (long)mB * Eq + nn) = rB;
        }
    }
}

// ---------------- flash attention (Br=64, Bc=32, d=64) ----------------
__global__ __launch_bounds__(256) void flash_kernel(
    const float* __restrict__ Q, const float* __restrict__ K,
    const float* __restrict__ V, float* __restrict__ O,
    const int* __restrict__ lens, int causal)
{
    __shared__ float Qs[64][64];
    __shared__ float Ks[32][64];
    __shared__ float Vs[32][64];
    __shared__ float Ss[64][33];
    __shared__ float ms[64], ls[64], al[64];

    const int tid = threadIdx.x;
    const int tx = tid & 15, ty = tid >> 4;
    const int bh = blockIdx.y;
    const int b = bh >> 4, h = bh & 15;
    const int q0 = blockIdx.x * 64;
    const int len = lens[b];

    {
        int r = tid >> 2;
        int c0 = (tid & 3) * 16;
        const float* qsrc = Q + ((long)(b*Lq + q0 + r))*Eq + h*DKq + c0;
#pragma unroll
        for (int p = 0; p < 4; p++)
            *(float4*)&Qs[r][c0 + p*4] = *(const float4*)(qsrc + p*4);
    }
    if (tid < 64) { ms[tid] = -INFINITY; ls[tid] = 0.f; }

    float o[4][4];
#pragma unroll
    for (int i = 0; i < 4; i++)
#pragma unroll
        for (int j = 0; j < 4; j++) o[i][j] = 0.f;

    const int kend = min(len, causal ? (q0 + 64) : Lq);
    __syncthreads();

    for (int k0 = 0; k0 < kend; k0 += 32) {
#pragma unroll
        for (int p = 0; p < 2; p++) {
            int r = (tid >> 4) + p*16, c = (tid & 15)*4;
            long gi = ((long)(b*Lq + k0 + r))*Eq + h*DKq + c;
            *(float4*)&Ks[r][c] = *(const float4*)(K + gi);
            *(float4*)&Vs[r][c] = *(const float4*)(V + gi);
        }
        __syncthreads();

        float s[4][2] = {{0.f,0.f},{0.f,0.f},{0.f,0.f},{0.f,0.f}};
#pragma unroll
        for (int kk = 0; kk < 64; kk += 4) {
            float4 qv[4];
            qv[0] = *(const float4*)&Qs[ty*4+0][kk];
            qv[1] = *(const float4*)&Qs[ty*4+1][kk];
            qv[2] = *(const float4*)&Qs[ty*4+2][kk];
            qv[3] = *(const float4*)&Qs[ty*4+3][kk];
            float4 kv[2];
            kv[0] = *(const float4*)&Ks[tx*2+0][kk];
            kv[1] = *(const float4*)&Ks[tx*2+1][kk];
#pragma unroll
            for (int i = 0; i < 4; i++)
#pragma unroll
                for (int j = 0; j < 2; j++)
                    s[i][j] += qv[i].x*kv[j].x + qv[i].y*kv[j].y
                             + qv[i].z*kv[j].z + qv[i].w*kv[j].w;
        }
#pragma unroll
        for (int ii = 0; ii < 4; ii++) {
            int ig = q0 + ty*4 + ii;
#pragma unroll
            for (int jj = 0; jj < 2; jj++) {
                int jg = k0 + tx*2 + jj;
                float e = s[ii][jj];
                if (jg >= len) e += NEGV;
                if (causal && jg > ig) e += NEGV;
                Ss[ty*4+ii][tx*2+jj] = e * SCALEV;
            }
        }
        __syncthreads();

        if (tid < 64) {
            float mo = ms[tid];
            float mx = mo;
#pragma unroll 8
            for (int j = 0; j < 32; j++) mx = fmaxf(mx, Ss[tid][j]);
            float a = __expf(mo - mx);
            float rs = 0.f;
#pragma unroll 8
            for (int j = 0; j < 32; j++) {
                float p = __expf(Ss[tid][j] - mx);
                Ss[tid][j] = p;
                rs += p;
            }
            ms[tid] = mx;
            ls[tid] = ls[tid]*a + rs;
            al[tid] = a;
        }
        __syncthreads();

        float a0 = al[ty*4+0], a1 = al[ty*4+1], a2 = al[ty*4+2], a3 = al[ty*4+3];
#pragma unroll
        for (int d = 0; d < 4; d++) {
            o[0][d] *= a0; o[1][d] *= a1; o[2][d] *= a2; o[3][d] *= a3;
        }
#pragma unroll 8
        for (int j = 0; j < 32; j++) {
            float4 v = *(const float4*)&Vs[j][tx*4];
            float p0 = Ss[ty*4+0][j], p1 = Ss[ty*4+1][j];
            float p2 = Ss[ty*4+2][j], p3 = Ss[ty*4+3][j];
            o[0][0] += p0*v.x; o[0][1] += p0*v.y; o[0][2] += p0*v.z; o[0][3] += p0*v.w;
            o[1][0] += p1*v.x; o[1][1] += p1*v.y; o[1][2] += p1*v.z; o[1][3] += p1*v.w;
            o[2][0] += p2*v.x; o[2][1] += p2*v.y; o[2][2] += p2*v.z; o[2][3] += p2*v.w;
            o[3][0] += p3*v.x; o[3][1] += p3*v.y; o[3][2] += p3*v.z; o[3][3] += p3*v.w;
        }
        __syncthreads();
    }

#pragma unroll
    for (int ii = 0; ii < 4; ii++) {
        int ig = q0 + ty*4 + ii;
        bool valid = ig < len;
        float inv = valid ? (1.f / ls[ty*4+ii]) : 0.f;
        float4 r;
        r.x = o[ii][0]*inv; r.y = o[ii][1]*inv;
        r.z = o[ii][2]*inv; r.w = o[ii][3]*inv;
        if (!valid) { r.x = 0.f; r.y = 0.f; r.z = 0.f; r.w = 0.f; }
        *(float4*)(O + ((long)(b*Lq + ig))*Eq + h*DKq + tx*4) = r;
    }
}

// ---------------- fused residual + layernorm ----------------
__global__ __launch_bounds__(256) void ln_kernel(
    const float* __restrict__ A, const float* __restrict__ Z,
    const float* __restrict__ g, const float* __restrict__ bb,
    float* __restrict__ out)
{
    __shared__ float sred[8], ssred[8];
    const int row = blockIdx.x, tid = threadIdx.x;
    const float4* a4 = (const float4*)(A + (long)row * Eq);
    const float4* z4 = (const float4*)(Z + (long)row * Eq);
    float4 av = a4[tid], zv = z4[tid];
    float4 t = make_float4(av.x+zv.x, av.y+zv.y, av.z+zv.z, av.w+zv.w);
    float s  = t.x + t.y + t.z + t.w;
    float ss = t.x*t.x + t.y*t.y + t.z*t.z + t.w*t.w;
#pragma unroll
    for (int o2 = 16; o2 > 0; o2 >>= 1) {
        s  += __shfl_xor_sync(0xffffffffu, s,  o2);
        ss += __shfl_xor_sync(0xffffffffu, ss, o2);
    }
    int wid = tid >> 5, lane = tid & 31;
    if (lane == 0) { sred[wid] = s; ssred[wid] = ss; }
    __syncthreads();
    if (tid < 8) {
        s = sred[tid]; ss = ssred[tid];
#pragma unroll
        for (int o2 = 4; o2 > 0; o2 >>= 1) {
            s  += __shfl_xor_sync(0xffu, s,  o2);
            ss += __shfl_xor_sync(0xffu, ss, o2);
        }
        if (tid == 0) { sred[0] = s; ssred[0] = ss; }
    }
    __syncthreads();
    const float mu  = sred[0] * (1.f / Eq);
    const float var = ssred[0] * (1.f / Eq) - mu * mu;
    const float rinv = rsqrtf(var + 1e-5f);
    float4 gv = ((const float4*)g)[tid];
    float4 bv = ((const float4*)bb)[tid];
    float4 r;
    r.x = (t.x - mu) * rinv * gv.x + bv.x;
    r.y = (t.y - mu) * rinv * gv.y + bv.y;
    r.z = (t.z - mu) * rinv * gv.z + bv.z;
    r.w = (t.w - mu) * rinv * gv.w + bv.w;
    ((float4*)(out + (long)row * Eq))[tid] = r;
}

// ---------------- launch ----------------
extern "C" void kernel_launch(void* const* d_in, const int* in_sizes, int n_in,
                              void* d_out, int out_size)
{
    const float* x    = (const float*)d_in[0];
    const float* ctx  = (const float*)d_in[1];
    const int*   lens = (const int*)  d_in[2];
    const float* Wq1  = (const float*)d_in[4];
    const float* Wk1  = (const float*)d_in[5];
    const float* Wv1  = (const float*)d_in[6];
    const float* Wq2  = (const float*)d_in[7];
    const float* Wk2  = (const float*)d_in[8];
    const float* Wv2  = (const float*)d_in[9];
    const float* ln1g = (const float*)d_in[10];
    const float* ln1b = (const float*)d_in[11];
    const float* ln2g = (const float*)d_in[12];
    const float* ln2b = (const float*)d_in[13];
    const float* ln3g = (const float*)d_in[14];
    const float* ln3b = (const float*)d_in[15];
    const float* fc1w = (const float*)d_in[16];
    const float* fc1b = (const float*)d_in[17];
    const float* fc2w = (const float*)d_in[18];
    const float* fc2b = (const float*)d_in[19];
    float* out = (float*)d_out;

    float *Qb, *Kb, *Vb, *Zb, *X1, *X2, *Hb;
    cudaGetSymbolAddress((void**)&Qb, g_Q);
    cudaGetSymbolAddress((void**)&Kb, g_K);
    cudaGetSymbolAddress((void**)&Vb, g_V);
    cudaGetSymbolAddress((void**)&Zb, g_Z);
    cudaGetSymbolAddress((void**)&X1, g_X1);
    cudaGetSymbolAddress((void**)&X2, g_X2);
    cudaGetSymbolAddress((void**)&Hb, g_Hb);

    const int SMEM_BYTES = 2 * 8192 * 4;  // 64 KB
    cudaFuncSetAttribute(gemm_mma, cudaFuncAttributeMaxDynamicSharedMemorySize,
                         SMEM_BYTES);

    dim3 gg(Mq/128, Eq/128);         // 64 x 8
    dim3 fg(Lq/64, Bq*Hq);           // 16 x 128
    const long PSTRIDE = (long)Eq * DKq;  // per-head weight stride

    // --- self attention ---
    gemm_mma<<<gg, 256, SMEM_BYTES>>>(x, Wq1, Qb, nullptr, lens, DKq, PSTRIDE, 6, 0);
    gemm_mma<<<gg, 256, SMEM_BYTES>>>(x, Wk1, Kb, nullptr, lens, DKq, PSTRIDE, 6, 0);
    gemm_mma<<<gg, 256, SMEM_BYTES>>>(x, Wv1, Vb, nullptr, lens, DKq, PSTRIDE, 6, 0);
    flash_kernel<<<fg, 256>>>(Qb, Kb, Vb, Zb, lens, 1);
    ln_kernel<<<Mq, 256>>>(x, Zb, ln1g, ln1b, X1);

    // --- cross attention (Q,K from context; V from x1) ---
    gemm_mma<<<gg, 256, SMEM_BYTES>>>(ctx, Wq2, Qb, nullptr, lens, DKq, PSTRIDE, 6, 0);
    gemm_mma<<<gg, 256, SMEM_BYTES>>>(ctx, Wk2, Kb, nullptr, lens, DKq, PSTRIDE, 6, 0);
    gemm_mma<<<gg, 256, SMEM_BYTES>>>(X1,  Wv2, Vb, nullptr, lens, DKq, PSTRIDE, 6, 0);
    flash_kernel<<<fg, 256>>>(Qb, Kb, Vb, Zb, lens, 0);
    ln_kernel<<<Mq, 256>>>(X1, Zb, ln2g, ln2b, X2);

    // --- FFN ---
    gemm_mma<<<gg, 256, SMEM_BYTES>>>(X2, fc1w, Hb, fc1b, lens, Eq, 0L, 10, 1);
    gemm_mma<<<gg, 256, SMEM_BYTES>>>(Hb, fc2w, Zb, fc2b, lens, Eq, 0L, 10, 0);
    ln_kernel<<<Mq, 256>>>(X2, Zb, ln3g, ln3b, out);
}

// round 6
// speedup vs baseline: 2.2356x; 1.6361x over previous
#include <cuda_runtime.h>
#include <math.h>
#include <stdint.h>

#define Bq   8
#define Lq   1024
#define Eq   1024
#define Hq   16
#define DKq  64
#define Mq   (Bq*Lq)
#define NEGV (-1000000000.0f)
#define SCALEV 0.125f

#define GK 1024
#define BKc 32
#define NIT (GK / BKc)

// ---------------- scratch (no cudaMalloc allowed) ----------------
__device__ float g_Q [Mq*Eq];
__device__ float g_K [Mq*Eq];
__device__ float g_V [Mq*Eq];
__device__ float g_Z [Mq*Eq];
__device__ float g_X1[Mq*Eq];
__device__ float g_X2[Mq*Eq];
__device__ float g_Hb[Mq*Eq];

__device__ __forceinline__ uint32_t f2tf32(float x) {
    uint32_t r; asm("cvt.rna.tf32.f32 %0, %1;" : "=r"(r) : "f"(x)); return r;
}

__device__ __forceinline__ void mma_tf32(float* c, const uint32_t* a,
                                         const uint32_t* b) {
    asm volatile(
        "mma.sync.aligned.m16n8k8.row.col.f32.tf32.tf32.f32 "
        "{%0,%1,%2,%3}, {%4,%5,%6,%7}, {%8,%9}, {%0,%1,%2,%3};"
        : "+f"(c[0]), "+f"(c[1]), "+f"(c[2]), "+f"(c[3])
        : "r"(a[0]), "r"(a[1]), "r"(a[2]), "r"(a[3]), "r"(b[0]), "r"(b[1]));
}

// ================= mma.sync tf32 GEMM, 128x128 tile, BK=32 =================
__global__ __launch_bounds__(256) void gemm_mma(
    const float* __restrict__ A, const float* __restrict__ W,
    float* __restrict__ C, const float* __restrict__ bias,
    const int* __restrict__ lens, int ldb, long bstride, int GRPs, int relu)
{
    extern __shared__ float sm[];
    const int tid = threadIdx.x;
    const int wid = tid >> 5, lane = tid & 31;
    const int warpm = wid >> 2, warpn = wid & 3;
    const int m0 = blockIdx.x * 128;
    const int n0 = blockIdx.y * 128;
    const int grpmask = (1 << GRPs) - 1;

    float acc[4][4][4];
#pragma unroll
    for (int mi = 0; mi < 4; mi++)
#pragma unroll
        for (int ni = 0; ni < 4; ni++)
#pragma unroll
            for (int c = 0; c < 4; c++) acc[mi][ni][c] = 0.f;

    float4 lA[4], lB[4];

    auto ldg_stage = [&](int k0) {
#pragma unroll
        for (int i = 0; i < 4; i++) {
            int idx = tid * 4 + i;
            int m = idx >> 3, kq = idx & 7;
            lA[i] = *(const float4*)(A + (long)(m0 + m) * GK + k0 + kq * 4);
        }
#pragma unroll
        for (int i = 0; i < 4; i++) {
            int idx = tid * 4 + i;
            int k = idx >> 5;
            int n4 = (idx & 31) * 4;
            const float* wp = W + ((long)((n0 + n4) >> GRPs)) * bstride
                                + (long)(k0 + k) * ldb + ((n0 + n4) & grpmask);
            lB[i] = *(const float4*)wp;
        }
    };

    auto sts_stage = [&](int s) {
        float* AF = sm + s * 8192;
        float* BF = AF + 4096;
#pragma unroll
        for (int i = 0; i < 4; i++) {
            int idx = tid * 4 + i;
            int m = idx >> 3, kq = idx & 7;
            int blk = (m >> 4) * 4 + (kq >> 1);
            int r = ((m & 15) >= 8 ? 1 : 0) + ((kq & 1) ? 2 : 0);
            uint32_t* p = (uint32_t*)(AF + blk * 128 + (m & 7) * 16 + r);
            p[0]  = f2tf32(lA[i].x);
            p[4]  = f2tf32(lA[i].y);
            p[8]  = f2tf32(lA[i].z);
            p[12] = f2tf32(lA[i].w);
        }
#pragma unroll
        for (int i = 0; i < 4; i++) {
            int idx = tid * 4 + i;
            int k = idx >> 5;
            int n4 = (idx & 31) * 4;
            int blk = (n4 >> 3) * 4 + (k >> 3);
            int r = ((k & 7) >= 4) ? 1 : 0;
            int lbase = (n4 & 7) * 4 + (k & 3);
            uint32_t* p = (uint32_t*)(BF + blk * 64 + lbase * 2 + r);
            p[0]  = f2tf32(lB[i].x);
            p[8]  = f2tf32(lB[i].y);
            p[16] = f2tf32(lB[i].z);
            p[24] = f2tf32(lB[i].w);
        }
    };

    auto compute_stage = [&](int s) {
        const float* AF = sm + s * 8192;
        const float* BF = AF + 4096;
#pragma unroll
        for (int ks = 0; ks < 4; ks++) {
            uint32_t af[4][4];
            uint32_t bf[4][2];
#pragma unroll
            for (int mi = 0; mi < 4; mi++)
                *(uint4*)af[mi] = *(const uint4*)
                    (AF + (((warpm * 4 + mi) * 4 + ks) * 32 + lane) * 4);
#pragma unroll
            for (int ni = 0; ni < 4; ni++)
                *(uint2*)bf[ni] = *(const uint2*)
                    (BF + (((warpn * 4 + ni) * 4 + ks) * 32 + lane) * 2);
#pragma unroll
            for (int mi = 0; mi < 4; mi++)
#pragma unroll
                for (int ni = 0; ni < 4; ni++)
                    mma_tf32(acc[mi][ni], af[mi], bf[ni]);
        }
    };

    ldg_stage(0);
    sts_stage(0);
    __syncthreads();

    for (int it = 0; it < NIT; it++) {
        const int s = it & 1;
        if (it + 1 < NIT) ldg_stage((it + 1) * BKc);
        compute_stage(s);
        if (it + 1 < NIT) {
            __syncthreads();
            sts_stage(s ^ 1);
            __syncthreads();
        }
    }

    const int g = lane >> 2, t2 = (lane & 3) * 2;
#pragma unroll
    for (int mi = 0; mi < 4; mi++) {
        int mA = m0 + warpm * 64 + mi * 16 + g;
        int mB = mA + 8;
        bool vA = (mA & 1023) < lens[mA >> 10];
        bool vB = (mB & 1023) < lens[mB >> 10];
#pragma unroll
        for (int ni = 0; ni < 4; ni++) {
            int nn = n0 + warpn * 32 + ni * 8 + t2;
            float bx = 0.f, by = 0.f;
            if (bias) { float2 bv = *(const float2*)(bias + nn); bx = bv.x; by = bv.y; }
            float2 rA, rB;
            rA.x = acc[mi][ni][0] + bx; rA.y = acc[mi][ni][1] + by;
            rB.x = acc[mi][ni][2] + bx; rB.y = acc[mi][ni][3] + by;
            if (relu) {
                rA.x = fmaxf(rA.x, 0.f); rA.y = fmaxf(rA.y, 0.f);
                rB.x = fmaxf(rB.x, 0.f); rB.y = fmaxf(rB.y, 0.f);
            }
            if (!vA) { rA.x = 0.f; rA.y = 0.f; }
            if (!vB) { rB.x = 0.f; rB.y = 0.f; }
            *(float2*)(C + (long)mA * Eq + nn) = rA;
            *(float2*)(C + (long)mB * Eq + nn) = rB;
        }
    }
}

// ============ flash attention on mma.sync tf32 (Br=64, Bc=64, d=64) ============
// 128 threads, 4 warps; warp w owns Q rows [w*16, w*16+16).
// KF: fragment-major K^T (S-mma B operand), blocks (nj,ks): KF[(nj*8+ks)*64 + lane*2 + r]
// VF: fragment-major V^T (PV-mma B operand), blocks (nd,kj): VF[(nd*8+kj)*64 + lane*2 + r]
// PF: per-warp A-fragment-major P: PF[w*1024 + kj*128 + lane*4 + r]
__global__ __launch_bounds__(128) void flash_mma(
    const float* __restrict__ Q, const float* __restrict__ K,
    const float* __restrict__ V, float* __restrict__ O,
    const int* __restrict__ lens, int causal)
{
    extern __shared__ float fsm[];
    float* KF = fsm;                         // 4096 floats
    float* VF = fsm + 4096;                  // 4096 floats
    uint32_t* PF = (uint32_t*)(fsm + 8192);  // 4096 words

    const int tid = threadIdx.x;
    const int w = tid >> 5, lane = tid & 31;
    const int g = lane >> 2, t = lane & 3;
    const int bh = blockIdx.y, b = bh >> 4, h = bh & 15;
    const int q0 = blockIdx.x * 64;
    const int len = lens[b];

    const long headBase = (long)(b * Lq) * Eq + h * DKq;
    const int ig0 = q0 + w * 16 + g;
    const int ig1 = ig0 + 8;

    // Q A-fragments in registers (rows ig0/ig1, k = ks*8 + t / t+4)
    uint32_t qf[8][4];
    {
        const float* qp = Q + headBase;
#pragma unroll
        for (int ks = 0; ks < 8; ks++) {
            int c = ks * 8 + t;
            qf[ks][0] = f2tf32(qp[(long)ig0 * Eq + c]);
            qf[ks][1] = f2tf32(qp[(long)ig1 * Eq + c]);
            qf[ks][2] = f2tf32(qp[(long)ig0 * Eq + c + 4]);
            qf[ks][3] = f2tf32(qp[(long)ig1 * Eq + c + 4]);
        }
    }

    float of[8][4];
#pragma unroll
    for (int nd = 0; nd < 8; nd++) {
        of[nd][0] = 0.f; of[nd][1] = 0.f; of[nd][2] = 0.f; of[nd][3] = 0.f;
    }
    float m0 = -INFINITY, m1 = -INFINITY, l0 = 0.f, l1 = 0.f;

    const int kend = (q0 >= len) ? 0
                   : (causal ? min(len, q0 + 64) : len);

    uint32_t* pfw = PF + w * 1024;

    for (int k0 = 0; k0 < kend; k0 += 64) {
        // ---- stage K, V^T tiles into fragment-major smem ----
        const long baseK = (long)(b * Lq + k0) * Eq + h * DKq;
#pragma unroll
        for (int i = 0; i < 8; i++) {
            int idx = tid + i * 128;           // 0..1023
            int j = idx >> 4, d4 = (idx & 15) * 4;
            long gi = baseK + (long)j * Eq + d4;
            float4 kv = *(const float4*)(K + gi);
            uint32_t* pk = (uint32_t*)&KF[((j >> 3) * 8 + (d4 >> 3)) * 64
                                          + ((j & 7) * 4) * 2 + ((d4 & 4) ? 1 : 0)];
            pk[0] = f2tf32(kv.x); pk[2] = f2tf32(kv.y);
            pk[4] = f2tf32(kv.z); pk[6] = f2tf32(kv.w);
            float4 vv = *(const float4*)(V + gi);
            uint32_t* pv = (uint32_t*)&VF[((d4 >> 3) * 8 + (j >> 3)) * 64
                                          + ((d4 & 7) * 4 + (j & 3)) * 2
                                          + ((j & 4) ? 1 : 0)];
            pv[0] = f2tf32(vv.x); pv[8] = f2tf32(vv.y);
            pv[16] = f2tf32(vv.z); pv[24] = f2tf32(vv.w);
        }
        __syncthreads();

        // ---- S = Q K^T ----
        float sf[8][4];
#pragma unroll
        for (int nj = 0; nj < 8; nj++) {
            sf[nj][0] = 0.f; sf[nj][1] = 0.f; sf[nj][2] = 0.f; sf[nj][3] = 0.f;
#pragma unroll
            for (int ks = 0; ks < 8; ks++) {
                uint32_t bf[2];
                *(uint2*)bf = *(const uint2*)&KF[(nj * 8 + ks) * 64 + lane * 2];
                mma_tf32(sf[nj], qf[ks], bf);
            }
        }

        // ---- masks + scale ----
        const bool needLen  = (k0 + 64 > len);
        const bool needDiag = causal && (k0 + 64 > q0);
        if (needLen || needDiag) {
#pragma unroll
            for (int nj = 0; nj < 8; nj++) {
                int jg0 = k0 + nj * 8 + 2 * t, jg1 = jg0 + 1;
                float a00 = (jg0 >= len ? NEGV : 0.f)
                          + (needDiag && jg0 > ig0 ? NEGV : 0.f);
                float a01 = (jg1 >= len ? NEGV : 0.f)
                          + (needDiag && jg1 > ig0 ? NEGV : 0.f);
                float a10 = (jg0 >= len ? NEGV : 0.f)
                          + (needDiag && jg0 > ig1 ? NEGV : 0.f);
                float a11 = (jg1 >= len ? NEGV : 0.f)
                          + (needDiag && jg1 > ig1 ? NEGV : 0.f);
                sf[nj][0] = (sf[nj][0] + a00) * SCALEV;
                sf[nj][1] = (sf[nj][1] + a01) * SCALEV;
                sf[nj][2] = (sf[nj][2] + a10) * SCALEV;
                sf[nj][3] = (sf[nj][3] + a11) * SCALEV;
            }
        } else {
#pragma unroll
            for (int nj = 0; nj < 8; nj++) {
                sf[nj][0] *= SCALEV; sf[nj][1] *= SCALEV;
                sf[nj][2] *= SCALEV; sf[nj][3] *= SCALEV;
            }
        }

        // ---- online softmax (quad-replicated row state) ----
        float rm0 = -INFINITY, rm1 = -INFINITY;
#pragma unroll
        for (int nj = 0; nj < 8; nj++) {
            rm0 = fmaxf(rm0, fmaxf(sf[nj][0], sf[nj][1]));
            rm1 = fmaxf(rm1, fmaxf(sf[nj][2], sf[nj][3]));
        }
        rm0 = fmaxf(rm0, __shfl_xor_sync(0xffffffffu, rm0, 1));
        rm0 = fmaxf(rm0, __shfl_xor_sync(0xffffffffu, rm0, 2));
        rm1 = fmaxf(rm1, __shfl_xor_sync(0xffffffffu, rm1, 1));
        rm1 = fmaxf(rm1, __shfl_xor_sync(0xffffffffu, rm1, 2));

        float nm0 = fmaxf(m0, rm0), nm1 = fmaxf(m1, rm1);
        float al0 = __expf(m0 - nm0), al1 = __expf(m1 - nm1);
        m0 = nm0; m1 = nm1;

        float rs0 = 0.f, rs1 = 0.f;
        const int lA = (g * 4 + ((2 * t) & 3)) * 4 + ((t >= 2) ? 2 : 0);
        const int lB = (g * 4 + ((2 * t + 1) & 3)) * 4 + ((t >= 2) ? 2 : 0);
#pragma unroll
        for (int nj = 0; nj < 8; nj++) {
            float p00 = __expf(sf[nj][0] - nm0);
            float p01 = __expf(sf[nj][1] - nm0);
            float p10 = __expf(sf[nj][2] - nm1);
            float p11 = __expf(sf[nj][3] - nm1);
            rs0 += p00 + p01;
            rs1 += p10 + p11;
            pfw[nj * 128 + lA]     = f2tf32(p00);
            pfw[nj * 128 + lA + 1] = f2tf32(p10);
            pfw[nj * 128 + lB]     = f2tf32(p01);
            pfw[nj * 128 + lB + 1] = f2tf32(p11);
        }
        rs0 += __shfl_xor_sync(0xffffffffu, rs0, 1);
        rs0 += __shfl_xor_sync(0xffffffffu, rs0, 2);
        rs1 += __shfl_xor_sync(0xffffffffu, rs1, 1);
        rs1 += __shfl_xor_sync(0xffffffffu, rs1, 2);
        l0 = l0 * al0 + rs0;
        l1 = l1 * al1 + rs1;

#pragma unroll
        for (int nd = 0; nd < 8; nd++) {
            of[nd][0] *= al0; of[nd][1] *= al0;
            of[nd][2] *= al1; of[nd][3] *= al1;
        }
        __syncwarp();

        // ---- O += P V ----
#pragma unroll
        for (int kj = 0; kj < 8; kj++) {
            uint32_t af[4];
            *(uint4*)af = *(const uint4*)&pfw[kj * 128 + lane * 4];
#pragma unroll
            for (int nd = 0; nd < 8; nd++) {
                uint32_t bf[2];
                *(uint2*)bf = *(const uint2*)&VF[(nd * 8 + kj) * 64 + lane * 2];
                mma_tf32(of[nd], af, bf);
            }
        }
        __syncthreads();
    }

    // ---- epilogue ----
    const bool v0 = ig0 < len, v1 = ig1 < len;
    const float inv0 = v0 ? (1.f / l0) : 0.f;
    const float inv1 = v1 ? (1.f / l1) : 0.f;
    float* op = O + headBase;
#pragma unroll
    for (int nd = 0; nd < 8; nd++) {
        int c = nd * 8 + 2 * t;
        float2 r0v, r1v;
        r0v.x = of[nd][0] * inv0; r0v.y = of[nd][1] * inv0;
        r1v.x = of[nd][2] * inv1; r1v.y = of[nd][3] * inv1;
        *(float2*)(op + (long)ig0 * Eq + c) = r0v;
        *(float2*)(op + (long)ig1 * Eq + c) = r1v;
    }
}

// ---------------- fused residual + layernorm ----------------
__global__ __launch_bounds__(256) void ln_kernel(
    const float* __restrict__ A, const float* __restrict__ Z,
    const float* __restrict__ g, const float* __restrict__ bb,
    float* __restrict__ out)
{
    __shared__ float sred[8], ssred[8];
    const int row = blockIdx.x, tid = threadIdx.x;
    const float4* a4 = (const float4*)(A + (long)row * Eq);
    const float4* z4 = (const float4*)(Z + (long)row * Eq);
    float4 av = a4[tid], zv = z4[tid];
    float4 t = make_float4(av.x+zv.x, av.y+zv.y, av.z+zv.z, av.w+zv.w);
    float s  = t.x + t.y + t.z + t.w;
    float ss = t.x*t.x + t.y*t.y + t.z*t.z + t.w*t.w;
#pragma unroll
    for (int o2 = 16; o2 > 0; o2 >>= 1) {
        s  += __shfl_xor_sync(0xffffffffu, s,  o2);
        ss += __shfl_xor_sync(0xffffffffu, ss, o2);
    }
    int wid = tid >> 5, lane = tid & 31;
    if (lane == 0) { sred[wid] = s; ssred[wid] = ss; }
    __syncthreads();
    if (tid < 8) {
        s = sred[tid]; ss = ssred[tid];
#pragma unroll
        for (int o2 = 4; o2 > 0; o2 >>= 1) {
            s  += __shfl_xor_sync(0xffu, s,  o2);
            ss += __shfl_xor_sync(0xffu, ss, o2);
        }
        if (tid == 0) { sred[0] = s; ssred[0] = ss; }
    }
    __syncthreads();
    const float mu  = sred[0] * (1.f / Eq);
    const float var = ssred[0] * (1.f / Eq) - mu * mu;
    const float rinv = rsqrtf(var + 1e-5f);
    float4 gv = ((const float4*)g)[tid];
    float4 bv = ((const float4*)bb)[tid];
    float4 r;
    r.x = (t.x - mu) * rinv * gv.x + bv.x;
    r.y = (t.y - mu) * rinv * gv.y + bv.y;
    r.z = (t.z - mu) * rinv * gv.z + bv.z;
    r.w = (t.w - mu) * rinv * gv.w + bv.w;
    ((float4*)(out + (long)row * Eq))[tid] = r;
}

// ---------------- launch ----------------
extern "C" void kernel_launch(void* const* d_in, const int* in_sizes, int n_in,
                              void* d_out, int out_size)
{
    const float* x    = (const float*)d_in[0];
    const float* ctx  = (const float*)d_in[1];
    const int*   lens = (const int*)  d_in[2];
    const float* Wq1  = (const float*)d_in[4];
    const float* Wk1  = (const float*)d_in[5];
    const float* Wv1  = (const float*)d_in[6];
    const float* Wq2  = (const float*)d_in[7];
    const float* Wk2  = (const float*)d_in[8];
    const float* Wv2  = (const float*)d_in[9];
    const float* ln1g = (const float*)d_in[10];
    const float* ln1b = (const float*)d_in[11];
    const float* ln2g = (const float*)d_in[12];
    const float* ln2b = (const float*)d_in[13];
    const float* ln3g = (const float*)d_in[14];
    const float* ln3b = (const float*)d_in[15];
    const float* fc1w = (const float*)d_in[16];
    const float* fc1b = (const float*)d_in[17];
    const float* fc2w = (const float*)d_in[18];
    const float* fc2b = (const float*)d_in[19];
    float* out = (float*)d_out;

    float *Qb, *Kb, *Vb, *Zb, *X1, *X2, *Hb;
    cudaGetSymbolAddress((void**)&Qb, g_Q);
    cudaGetSymbolAddress((void**)&Kb, g_K);
    cudaGetSymbolAddress((void**)&Vb, g_V);
    cudaGetSymbolAddress((void**)&Zb, g_Z);
    cudaGetSymbolAddress((void**)&X1, g_X1);
    cudaGetSymbolAddress((void**)&X2, g_X2);
    cudaGetSymbolAddress((void**)&Hb, g_Hb);

    const int SMEM_G = 2 * 8192 * 4;   // 64 KB for gemm
    const int SMEM_F = 12288 * 4;      // 48 KB for flash
    cudaFuncSetAttribute(gemm_mma, cudaFuncAttributeMaxDynamicSharedMemorySize,
                         SMEM_G);
    cudaFuncSetAttribute(flash_mma, cudaFuncAttributeMaxDynamicSharedMemorySize,
                         SMEM_F);

    dim3 gg(Mq/128, Eq/128);         // 64 x 8
    dim3 fg(Lq/64, Bq*Hq);           // 16 x 128
    const long PSTRIDE = (long)Eq * DKq;  // per-head weight stride

    // --- self attention ---
    gemm_mma<<<gg, 256, SMEM_G>>>(x, Wq1, Qb, nullptr, lens, DKq, PSTRIDE, 6, 0);
    gemm_mma<<<gg, 256, SMEM_G>>>(x, Wk1, Kb, nullptr, lens, DKq, PSTRIDE, 6, 0);
    gemm_mma<<<gg, 256, SMEM_G>>>(x, Wv1, Vb, nullptr, lens, DKq, PSTRIDE, 6, 0);
    flash_mma<<<fg, 128, SMEM_F>>>(Qb, Kb, Vb, Zb, lens, 1);
    ln_kernel<<<Mq, 256>>>(x, Zb, ln1g, ln1b, X1);

    // --- cross attention (Q,K from context; V from x1) ---
    gemm_mma<<<gg, 256, SMEM_G>>>(ctx, Wq2, Qb, nullptr, lens, DKq, PSTRIDE, 6, 0);
    gemm_mma<<<gg, 256, SMEM_G>>>(ctx, Wk2, Kb, nullptr, lens, DKq, PSTRIDE, 6, 0);
    gemm_mma<<<gg, 256, SMEM_G>>>(X1,  Wv2, Vb, nullptr, lens, DKq, PSTRIDE, 6, 0);
    flash_mma<<<fg, 128, SMEM_F>>>(Qb, Kb, Vb, Zb, lens, 0);
    ln_kernel<<<Mq, 256>>>(X1, Zb, ln2g, ln2b, X2);

    // --- FFN ---
    gemm_mma<<<gg, 256, SMEM_G>>>(X2, fc1w, Hb, fc1b, lens, Eq, 0L, 10, 1);
    gemm_mma<<<gg, 256, SMEM_G>>>(Hb, fc2w, Zb, fc2b, lens, Eq, 0L, 10, 0);
    ln_kernel<<<Mq, 256>>>(X2, Zb, ln3g, ln3b, out);
}

// round 7
// speedup vs baseline: 4.7125x; 2.1079x over previous
#include <cuda_runtime.h>
#include <math.h>
#include <stdint.h>

#define Bq   8
#define Lq   1024
#define Eq   1024
#define Hq   16
#define DKq  64
#define Mq   (Bq*Lq)
#define NEGV (-1000000000.0f)
#define SCALEV 0.125f

#define GK 1024
#define BKc 32
#define NIT (GK / BKc)

// ---------------- scratch (no cudaMalloc allowed) ----------------
__device__ float g_Q [Mq*Eq];
__device__ float g_K [Mq*Eq];
__device__ float g_V [Mq*Eq];
__device__ float g_Z [Mq*Eq];
__device__ float g_X1[Mq*Eq];
__device__ float g_X2[Mq*Eq];
__device__ float g_Hb[Mq*Eq];
__device__ float g_Wt[8u * 1024u * 1024u];   // 8 transposed weight matrices

__device__ __forceinline__ uint32_t f2tf32(float x) {
    uint32_t r; asm("cvt.rna.tf32.f32 %0, %1;" : "=r"(r) : "f"(x)); return r;
}
__device__ __forceinline__ uint32_t smem_u32(const void* p) {
    uint32_t a;
    asm("{ .reg .u64 t; cvta.to.shared.u64 t, %1; cvt.u32.u64 %0, t; }"
        : "=r"(a) : "l"(p));
    return a;
}
__device__ __forceinline__ void mma_tf32(float* c, const uint32_t* a,
                                         const uint32_t* b) {
    asm volatile(
        "mma.sync.aligned.m16n8k8.row.col.f32.tf32.tf32.f32 "
        "{%0,%1,%2,%3}, {%4,%5,%6,%7}, {%8,%9}, {%0,%1,%2,%3};"
        : "+f"(c[0]), "+f"(c[1]), "+f"(c[2]), "+f"(c[3])
        : "r"(a[0]), "r"(a[1]), "r"(a[2]), "r"(a[3]), "r"(b[0]), "r"(b[1]));
}
__device__ __forceinline__ void ldsm_x4(uint32_t* r, uint32_t addr) {
    asm volatile("ldmatrix.sync.aligned.m8n8.x4.shared.b16 {%0,%1,%2,%3}, [%4];"
        : "=r"(r[0]), "=r"(r[1]), "=r"(r[2]), "=r"(r[3]) : "r"(addr));
}
__device__ __forceinline__ void cp16(uint32_t saddr, const void* g) {
    asm volatile("cp.async.cg.shared.global [%0], [%1], 16;"
                 :: "r"(saddr), "l"(g));
}

// ------------- weight transpose: Wt[n*1024 + k] = W(k, n) -------------
// W(k,n) = W[(n>>GRPs)*bstride + k*ldb + (n & ((1<<GRPs)-1))]
__global__ __launch_bounds__(256) void wtr_kernel(
    const float* __restrict__ W, float* __restrict__ Wt,
    int ldb, long bstride, int GRPs)
{
    __shared__ float ts[32][33];
    const int k0 = blockIdx.x * 32, n0 = blockIdx.y * 32;
    const int tx = threadIdx.x & 31, ty = threadIdx.x >> 5;
    const int mask = (1 << GRPs) - 1;
#pragma unroll
    for (int j = 0; j < 4; j++) {
        int k = k0 + ty + j * 8;
        int n = n0 + tx;
        ts[ty + j * 8][tx] =
            W[((long)(n >> GRPs)) * bstride + (long)k * ldb + (n & mask)];
    }
    __syncthreads();
#pragma unroll
    for (int j = 0; j < 4; j++) {
        int n = n0 + ty + j * 8;
        Wt[(long)n * 1024 + k0 + tx] = ts[tx][ty + j * 8];
    }
}

// ====== mma.sync tf32 GEMM: cp.async + swizzled smem + ldmatrix ======
// A row-major [M][1024], Wt n-major [N][1024]. 128x128 tile, BK=32, 3 stages.
#define NST 3
__global__ __launch_bounds__(256) void gemm_mma(
    const float* __restrict__ A, const float* __restrict__ Wt,
    float* __restrict__ C, const float* __restrict__ bias,
    const int* __restrict__ lens, int relu)
{
    extern __shared__ float sm[];
    const uint32_t smemBase = smem_u32(sm);
    const int tid = threadIdx.x;
    const int wid = tid >> 5, lane = tid & 31;
    const int warpm = wid >> 2, warpn = wid & 3;
    const int m0 = blockIdx.x * 128;
    const int n0 = blockIdx.y * 128;

    float acc[4][4][4];
#pragma unroll
    for (int mi = 0; mi < 4; mi++)
#pragma unroll
        for (int ni = 0; ni < 4; ni++)
#pragma unroll
            for (int c = 0; c < 4; c++) acc[mi][ni][c] = 0.f;

    // stage slot: A at slot*32768 B, B at +16384 B. rows 128B, 8 chunks, swizzled.
    auto load_stage = [&](int slot, int k0) {
        uint32_t sb = smemBase + slot * 32768;
#pragma unroll
        for (int i = 0; i < 4; i++) {
            int m = (tid >> 3) + i * 32;
            int c = tid & 7;
            uint32_t off = (uint32_t)(m * 128 + ((c ^ (m & 7)) * 16));
            cp16(sb + off,          A  + (long)(m0 + m) * GK + k0 + c * 4);
            cp16(sb + 16384 + off,  Wt + (long)(n0 + m) * GK + k0 + c * 4);
        }
        asm volatile("cp.async.commit_group;" ::: "memory");
    };

    auto compute_stage = [&](int slot) {
        const uint32_t sA = smemBase + slot * 32768;
        const uint32_t sB = sA + 16384;
        const int sw = lane & 7;
        const int rA = warpm * 64 + (lane & 7) + ((lane >> 3) & 1) * 8;
        const int hiA = (lane >> 4) & 1;
        const int rB = warpn * 32 + (lane & 7);
        const int cBh = lane >> 3;                 // 0..3
#pragma unroll
        for (int ksp = 0; ksp < 2; ksp++) {
            uint32_t bfr[4][4];
#pragma unroll
            for (int ni = 0; ni < 4; ni++)
                ldsm_x4(bfr[ni], sB + (uint32_t)((rB + ni * 8) * 128
                          + (((ksp * 4 + cBh) ^ sw) * 16)));
#pragma unroll
            for (int half = 0; half < 2; half++) {
                const int ks = ksp * 2 + half;
                const uint32_t cA = (uint32_t)(((ks * 2 + hiA) ^ sw) * 16);
#pragma unroll
                for (int mi = 0; mi < 4; mi++) {
                    uint32_t afr[4];
                    ldsm_x4(afr, sA + (uint32_t)((rA + mi * 16) * 128) + cA);
#pragma unroll
                    for (int ni = 0; ni < 4; ni++)
                        mma_tf32(acc[mi][ni], afr, bfr[ni] + half * 2);
                }
            }
        }
    };

    load_stage(0, 0);
    load_stage(1, BKc);
    asm volatile("cp.async.wait_group 1;" ::: "memory");
    __syncthreads();

    for (int it = 0; it < NIT; it++) {
        compute_stage(it % NST);
        if (it + 2 < NIT) {
            load_stage((it + 2) % NST, (it + 2) * BKc);
            asm volatile("cp.async.wait_group 1;" ::: "memory");
        } else {
            asm volatile("cp.async.wait_group 0;" ::: "memory");
        }
        __syncthreads();
    }

    // ---- epilogue ----
    const int g = lane >> 2, t2 = (lane & 3) * 2;
#pragma unroll
    for (int mi = 0; mi < 4; mi++) {
        int mA = m0 + warpm * 64 + mi * 16 + g;
        int mB = mA + 8;
        bool vA = (mA & 1023) < lens[mA >> 10];
        bool vB = (mB & 1023) < lens[mB >> 10];
#pragma unroll
        for (int ni = 0; ni < 4; ni++) {
            int nn = n0 + warpn * 32 + ni * 8 + t2;
            float bx = 0.f, by = 0.f;
            if (bias) { float2 bv = *(const float2*)(bias + nn); bx = bv.x; by = bv.y; }
            float2 rA, rB;
            rA.x = acc[mi][ni][0] + bx; rA.y = acc[mi][ni][1] + by;
            rB.x = acc[mi][ni][2] + bx; rB.y = acc[mi][ni][3] + by;
            if (relu) {
                rA.x = fmaxf(rA.x, 0.f); rA.y = fmaxf(rA.y, 0.f);
                rB.x = fmaxf(rB.x, 0.f); rB.y = fmaxf(rB.y, 0.f);
            }
            if (!vA) { rA.x = 0.f; rA.y = 0.f; }
            if (!vB) { rB.x = 0.f; rB.y = 0.f; }
            *(float2*)(C + (long)mA * Eq + nn) = rA;
            *(float2*)(C + (long)mB * Eq + nn) = rB;
        }
    }
}

// ============ flash attention on mma.sync tf32 (Br=64, Bc=64, d=64) ============
__global__ __launch_bounds__(128) void flash_mma(
    const float* __restrict__ Q, const float* __restrict__ K,
    const float* __restrict__ V, float* __restrict__ O,
    const int* __restrict__ lens, int causal)
{
    extern __shared__ float fsm[];
    float* KF = fsm;                         // 4096 floats
    float* VF = fsm + 4096;                  // 4096 floats
    uint32_t* PF = (uint32_t*)(fsm + 8192);  // 4096 words

    const int tid = threadIdx.x;
    const int w = tid >> 5, lane = tid & 31;
    const int g = lane >> 2, t = lane & 3;
    const int bh = blockIdx.y, b = bh >> 4, h = bh & 15;
    const int q0 = blockIdx.x * 64;
    const int len = lens[b];

    const long headBase = (long)(b * Lq) * Eq + h * DKq;
    const int ig0 = q0 + w * 16 + g;
    const int ig1 = ig0 + 8;

    uint32_t qf[8][4];
    {
        const float* qp = Q + headBase;
#pragma unroll
        for (int ks = 0; ks < 8; ks++) {
            int c = ks * 8 + t;
            qf[ks][0] = f2tf32(qp[(long)ig0 * Eq + c]);
            qf[ks][1] = f2tf32(qp[(long)ig1 * Eq + c]);
            qf[ks][2] = f2tf32(qp[(long)ig0 * Eq + c + 4]);
            qf[ks][3] = f2tf32(qp[(long)ig1 * Eq + c + 4]);
        }
    }

    float of[8][4];
#pragma unroll
    for (int nd = 0; nd < 8; nd++) {
        of[nd][0] = 0.f; of[nd][1] = 0.f; of[nd][2] = 0.f; of[nd][3] = 0.f;
    }
    float m0 = -INFINITY, m1 = -INFINITY, l0 = 0.f, l1 = 0.f;

    const int kend = (q0 >= len) ? 0 : (causal ? min(len, q0 + 64) : len);
    uint32_t* pfw = PF + w * 1024;

    for (int k0 = 0; k0 < kend; k0 += 64) {
        const long baseK = (long)(b * Lq + k0) * Eq + h * DKq;
#pragma unroll
        for (int i = 0; i < 8; i++) {
            int idx = tid + i * 128;
            int j = idx >> 4, d4 = (idx & 15) * 4;
            long gi = baseK + (long)j * Eq + d4;
            float4 kv = *(const float4*)(K + gi);
            uint32_t* pk = (uint32_t*)&KF[((j >> 3) * 8 + (d4 >> 3)) * 64
                                          + ((j & 7) * 4) * 2 + ((d4 & 4) ? 1 : 0)];
            pk[0] = f2tf32(kv.x); pk[2] = f2tf32(kv.y);
            pk[4] = f2tf32(kv.z); pk[6] = f2tf32(kv.w);
            float4 vv = *(const float4*)(V + gi);
            uint32_t* pv = (uint32_t*)&VF[((d4 >> 3) * 8 + (j >> 3)) * 64
                                          + ((d4 & 7) * 4 + (j & 3)) * 2
                                          + ((j & 4) ? 1 : 0)];
            pv[0] = f2tf32(vv.x); pv[8] = f2tf32(vv.y);
            pv[16] = f2tf32(vv.z); pv[24] = f2tf32(vv.w);
        }
        __syncthreads();

        float sf[8][4];
#pragma unroll
        for (int nj = 0; nj < 8; nj++) {
            sf[nj][0] = 0.f; sf[nj][1] = 0.f; sf[nj][2] = 0.f; sf[nj][3] = 0.f;
#pragma unroll
            for (int ks = 0; ks < 8; ks++) {
                uint32_t bf[2];
                *(uint2*)bf = *(const uint2*)&KF[(nj * 8 + ks) * 64 + lane * 2];
                mma_tf32(sf[nj], qf[ks], bf);
            }
        }

        const bool needLen  = (k0 + 64 > len);
        const bool needDiag = causal && (k0 + 64 > q0);
        if (needLen || needDiag) {
#pragma unroll
            for (int nj = 0; nj < 8; nj++) {
                int jg0 = k0 + nj * 8 + 2 * t, jg1 = jg0 + 1;
                float a00 = (jg0 >= len ? NEGV : 0.f)
                          + (needDiag && jg0 > ig0 ? NEGV : 0.f);
                float a01 = (jg1 >= len ? NEGV : 0.f)
                          + (needDiag && jg1 > ig0 ? NEGV : 0.f);
                float a10 = (jg0 >= len ? NEGV : 0.f)
                          + (needDiag && jg0 > ig1 ? NEGV : 0.f);
                float a11 = (jg1 >= len ? NEGV : 0.f)
                          + (needDiag && jg1 > ig1 ? NEGV : 0.f);
                sf[nj][0] = (sf[nj][0] + a00) * SCALEV;
                sf[nj][1] = (sf[nj][1] + a01) * SCALEV;
                sf[nj][2] = (sf[nj][2] + a10) * SCALEV;
                sf[nj][3] = (sf[nj][3] + a11) * SCALEV;
            }
        } else {
#pragma unroll
            for (int nj = 0; nj < 8; nj++) {
                sf[nj][0] *= SCALEV; sf[nj][1] *= SCALEV;
                sf[nj][2] *= SCALEV; sf[nj][3] *= SCALEV;
            }
        }

        float rm0 = -INFINITY, rm1 = -INFINITY;
#pragma unroll
        for (int nj = 0; nj < 8; nj++) {
            rm0 = fmaxf(rm0, fmaxf(sf[nj][0], sf[nj][1]));
            rm1 = fmaxf(rm1, fmaxf(sf[nj][2], sf[nj][3]));
        }
        rm0 = fmaxf(rm0, __shfl_xor_sync(0xffffffffu, rm0, 1));
        rm0 = fmaxf(rm0, __shfl_xor_sync(0xffffffffu, rm0, 2));
        rm1 = fmaxf(rm1, __shfl_xor_sync(0xffffffffu, rm1, 1));
        rm1 = fmaxf(rm1, __shfl_xor_sync(0xffffffffu, rm1, 2));

        float nm0 = fmaxf(m0, rm0), nm1 = fmaxf(m1, rm1);
        float al0 = __expf(m0 - nm0), al1 = __expf(m1 - nm1);
        m0 = nm0; m1 = nm1;

        float rs0 = 0.f, rs1 = 0.f;
        const int lA = (g * 4 + ((2 * t) & 3)) * 4 + ((t >= 2) ? 2 : 0);
        const int lB = (g * 4 + ((2 * t + 1) & 3)) * 4 + ((t >= 2) ? 2 : 0);
#pragma unroll
        for (int nj = 0; nj < 8; nj++) {
            float p00 = __expf(sf[nj][0] - nm0);
            float p01 = __expf(sf[nj][1] - nm0);
            float p10 = __expf(sf[nj][2] - nm1);
            float p11 = __expf(sf[nj][3] - nm1);
            rs0 += p00 + p01;
            rs1 += p10 + p11;
            pfw[nj * 128 + lA]     = f2tf32(p00);
            pfw[nj * 128 + lA + 1] = f2tf32(p10);
            pfw[nj * 128 + lB]     = f2tf32(p01);
            pfw[nj * 128 + lB + 1] = f2tf32(p11);
        }
        rs0 += __shfl_xor_sync(0xffffffffu, rs0, 1);
        rs0 += __shfl_xor_sync(0xffffffffu, rs0, 2);
        rs1 += __shfl_xor_sync(0xffffffffu, rs1, 1);
        rs1 += __shfl_xor_sync(0xffffffffu, rs1, 2);
        l0 = l0 * al0 + rs0;
        l1 = l1 * al1 + rs1;

#pragma unroll
        for (int nd = 0; nd < 8; nd++) {
            of[nd][0] *= al0; of[nd][1] *= al0;
            of[nd][2] *= al1; of[nd][3] *= al1;
        }
        __syncwarp();

#pragma unroll
        for (int kj = 0; kj < 8; kj++) {
            uint32_t af[4];
            *(uint4*)af = *(const uint4*)&pfw[kj * 128 + lane * 4];
#pragma unroll
            for (int nd = 0; nd < 8; nd++) {
                uint32_t bf[2];
                *(uint2*)bf = *(const uint2*)&VF[(nd * 8 + kj) * 64 + lane * 2];
                mma_tf32(of[nd], af, bf);
            }
        }
        __syncthreads();
    }

    const bool v0 = ig0 < len, v1 = ig1 < len;
    const float inv0 = v0 ? (1.f / l0) : 0.f;
    const float inv1 = v1 ? (1.f / l1) : 0.f;
    float* op = O + headBase;
#pragma unroll
    for (int nd = 0; nd < 8; nd++) {
        int c = nd * 8 + 2 * t;
        float2 r0v, r1v;
        r0v.x = of[nd][0] * inv0; r0v.y = of[nd][1] * inv0;
        r1v.x = of[nd][2] * inv1; r1v.y = of[nd][3] * inv1;
        *(float2*)(op + (long)ig0 * Eq + c) = r0v;
        *(float2*)(op + (long)ig1 * Eq + c) = r1v;
    }
}

// ---------------- fused residual + layernorm ----------------
__global__ __launch_bounds__(256) void ln_kernel(
    const float* __restrict__ A, const float* __restrict__ Z,
    const float* __restrict__ g, const float* __restrict__ bb,
    float* __restrict__ out)
{
    __shared__ float sred[8], ssred[8];
    const int row = blockIdx.x, tid = threadIdx.x;
    const float4* a4 = (const float4*)(A + (long)row * Eq);
    const float4* z4 = (const float4*)(Z + (long)row * Eq);
    float4 av = a4[tid], zv = z4[tid];
    float4 t = make_float4(av.x+zv.x, av.y+zv.y, av.z+zv.z, av.w+zv.w);
    float s  = t.x + t.y + t.z + t.w;
    float ss = t.x*t.x + t.y*t.y + t.z*t.z + t.w*t.w;
#pragma unroll
    for (int o2 = 16; o2 > 0; o2 >>= 1) {
        s  += __shfl_xor_sync(0xffffffffu, s,  o2);
        ss += __shfl_xor_sync(0xffffffffu, ss, o2);
    }
    int wid = tid >> 5, lane = tid & 31;
    if (lane == 0) { sred[wid] = s; ssred[wid] = ss; }
    __syncthreads();
    if (tid < 8) {
        s = sred[tid]; ss = ssred[tid];
#pragma unroll
        for (int o2 = 4; o2 > 0; o2 >>= 1) {
            s  += __shfl_xor_sync(0xffu, s,  o2);
            ss += __shfl_xor_sync(0xffu, ss, o2);
        }
        if (tid == 0) { sred[0] = s; ssred[0] = ss; }
    }
    __syncthreads();
    const float mu  = sred[0] * (1.f / Eq);
    const float var = ssred[0] * (1.f / Eq) - mu * mu;
    const float rinv = rsqrtf(var + 1e-5f);
    float4 gv = ((const float4*)g)[tid];
    float4 bv = ((const float4*)bb)[tid];
    float4 r;
    r.x = (t.x - mu) * rinv * gv.x + bv.x;
    r.y = (t.y - mu) * rinv * gv.y + bv.y;
    r.z = (t.z - mu) * rinv * gv.z + bv.z;
    r.w = (t.w - mu) * rinv * gv.w + bv.w;
    ((float4*)(out + (long)row * Eq))[tid] = r;
}

// ---------------- launch ----------------
extern "C" void kernel_launch(void* const* d_in, const int* in_sizes, int n_in,
                              void* d_out, int out_size)
{
    const float* x    = (const float*)d_in[0];
    const float* ctx  = (const float*)d_in[1];
    const int*   lens = (const int*)  d_in[2];
    const float* Wq1  = (const float*)d_in[4];
    const float* Wk1  = (const float*)d_in[5];
    const float* Wv1  = (const float*)d_in[6];
    const float* Wq2  = (const float*)d_in[7];
    const float* Wk2  = (const float*)d_in[8];
    const float* Wv2  = (const float*)d_in[9];
    const float* ln1g = (const float*)d_in[10];
    const float* ln1b = (const float*)d_in[11];
    const float* ln2g = (const float*)d_in[12];
    const float* ln2b = (const float*)d_in[13];
    const float* ln3g = (const float*)d_in[14];
    const float* ln3b = (const float*)d_in[15];
    const float* fc1w = (const float*)d_in[16];
    const float* fc1b = (const float*)d_in[17];
    const float* fc2w = (const float*)d_in[18];
    const float* fc2b = (const float*)d_in[19];
    float* out = (float*)d_out;

    float *Qb, *Kb, *Vb, *Zb, *X1, *X2, *Hb, *Wt;
    cudaGetSymbolAddress((void**)&Qb, g_Q);
    cudaGetSymbolAddress((void**)&Kb, g_K);
    cudaGetSymbolAddress((void**)&Vb, g_V);
    cudaGetSymbolAddress((void**)&Zb, g_Z);
    cudaGetSymbolAddress((void**)&X1, g_X1);
    cudaGetSymbolAddress((void**)&X2, g_X2);
    cudaGetSymbolAddress((void**)&Hb, g_Hb);
    cudaGetSymbolAddress((void**)&Wt, g_Wt);
#define WT(i) (Wt + (size_t)(i) * 1048576u)

    const int SMEM_G = NST * 32768;    // 96 KB for gemm
    const int SMEM_F = 12288 * 4;      // 48 KB for flash
    cudaFuncSetAttribute(gemm_mma, cudaFuncAttributeMaxDynamicSharedMemorySize,
                         SMEM_G);
    cudaFuncSetAttribute(flash_mma, cudaFuncAttributeMaxDynamicSharedMemorySize,
                         SMEM_F);

    dim3 tg(32, 32);
    const long PSTRIDE = (long)Eq * DKq;
    // transpose all 8 weights into n-major layout
    wtr_kernel<<<tg, 256>>>(Wq1,  WT(0), DKq, PSTRIDE, 6);
    wtr_kernel<<<tg, 256>>>(Wk1,  WT(1), DKq, PSTRIDE, 6);
    wtr_kernel<<<tg, 256>>>(Wv1,  WT(2), DKq, PSTRIDE, 6);
    wtr_kernel<<<tg, 256>>>(Wq2,  WT(3), DKq, PSTRIDE, 6);
    wtr_kernel<<<tg, 256>>>(Wk2,  WT(4), DKq, PSTRIDE, 6);
    wtr_kernel<<<tg, 256>>>(Wv2,  WT(5), DKq, PSTRIDE, 6);
    wtr_kernel<<<tg, 256>>>(fc1w, WT(6), Eq,  0L,      10);
    wtr_kernel<<<tg, 256>>>(fc2w, WT(7), Eq,  0L,      10);

    dim3 gg(Mq/128, Eq/128);         // 64 x 8
    dim3 fg(Lq/64, Bq*Hq);           // 16 x 128

    // --- self attention ---
    gemm_mma<<<gg, 256, SMEM_G>>>(x, WT(0), Qb, nullptr, lens, 0);
    gemm_mma<<<gg, 256, SMEM_G>>>(x, WT(1), Kb, nullptr, lens, 0);
    gemm_mma<<<gg, 256, SMEM_G>>>(x, WT(2), Vb, nullptr, lens, 0);
    flash_mma<<<fg, 128, SMEM_F>>>(Qb, Kb, Vb, Zb, lens, 1);
    ln_kernel<<<Mq, 256>>>(x, Zb, ln1g, ln1b, X1);

    // --- cross attention (Q,K from context; V from x1) ---
    gemm_mma<<<gg, 256, SMEM_G>>>(ctx, WT(3), Qb, nullptr, lens, 0);
    gemm_mma<<<gg, 256, SMEM_G>>>(ctx, WT(4), Kb, nullptr, lens, 0);
    gemm_mma<<<gg, 256, SMEM_G>>>(X1,  WT(5), Vb, nullptr, lens, 0);
    flash_mma<<<fg, 128, SMEM_F>>>(Qb, Kb, Vb, Zb, lens, 0);
    ln_kernel<<<Mq, 256>>>(X1, Zb, ln2g, ln2b, X2);

    // --- FFN ---
    gemm_mma<<<gg, 256, SMEM_G>>>(X2, WT(6), Hb, fc1b, lens, 1);
    gemm_mma<<<gg, 256, SMEM_G>>>(Hb, WT(7), Zb, fc2b, lens, 0);
    ln_kernel<<<Mq, 256>>>(X2, Zb, ln3g, ln3b, out);
}

// round 8
// speedup vs baseline: 7.2124x; 1.5305x over previous
#include <cuda_runtime.h>
#include <cuda_fp16.h>
#include <math.h>
#include <stdint.h>

#define Bq   8
#define Lq   1024
#define Eq   1024
#define Hq   16
#define DKq  64
#define Mq   (Bq*Lq)
#define NEGV (-1000000000.0f)
#define SCALEV 0.125f

#define GK   1024
#define BKH  64
#define NITH (GK / BKH)
#define NST  3

// ---------------- scratch (no cudaMalloc allowed) ----------------
__device__ float g_Q [Mq*Eq];
__device__ float g_K [Mq*Eq];
__device__ float g_V [Mq*Eq];
__device__ float g_Z [Mq*Eq];
__device__ float g_X1[Mq*Eq];
__device__ float g_X2[Mq*Eq];
__device__ __half g_xh  [Mq*Eq];
__device__ __half g_ctxh[Mq*Eq];
__device__ __half g_X1h [Mq*Eq];
__device__ __half g_X2h [Mq*Eq];
__device__ __half g_Hbh [Mq*Eq];
__device__ __half g_Wt  [8u * 1024u * 1024u];   // 8 transposed fp16 weights

__device__ __forceinline__ uint32_t f2tf32(float x) {
    uint32_t r; asm("cvt.rna.tf32.f32 %0, %1;" : "=r"(r) : "f"(x)); return r;
}
__device__ __forceinline__ uint32_t smem_u32(const void* p) {
    uint32_t a;
    asm("{ .reg .u64 t; cvta.to.shared.u64 t, %1; cvt.u32.u64 %0, t; }"
        : "=r"(a) : "l"(p));
    return a;
}
__device__ __forceinline__ void mma_tf32(float* c, const uint32_t* a,
                                         const uint32_t* b) {
    asm volatile(
        "mma.sync.aligned.m16n8k8.row.col.f32.tf32.tf32.f32 "
        "{%0,%1,%2,%3}, {%4,%5,%6,%7}, {%8,%9}, {%0,%1,%2,%3};"
        : "+f"(c[0]), "+f"(c[1]), "+f"(c[2]), "+f"(c[3])
        : "r"(a[0]), "r"(a[1]), "r"(a[2]), "r"(a[3]), "r"(b[0]), "r"(b[1]));
}
__device__ __forceinline__ void mma_f16(float* c, const uint32_t* a,
                                        const uint32_t* b) {
    asm volatile(
        "mma.sync.aligned.m16n8k16.row.col.f32.f16.f16.f32 "
        "{%0,%1,%2,%3}, {%4,%5,%6,%7}, {%8,%9}, {%0,%1,%2,%3};"
        : "+f"(c[0]), "+f"(c[1]), "+f"(c[2]), "+f"(c[3])
        : "r"(a[0]), "r"(a[1]), "r"(a[2]), "r"(a[3]), "r"(b[0]), "r"(b[1]));
}
__device__ __forceinline__ void ldsm_x4(uint32_t* r, uint32_t addr) {
    asm volatile("ldmatrix.sync.aligned.m8n8.x4.shared.b16 {%0,%1,%2,%3}, [%4];"
        : "=r"(r[0]), "=r"(r[1]), "=r"(r[2]), "=r"(r[3]) : "r"(addr));
}
__device__ __forceinline__ void cp16(uint32_t saddr, const void* g) {
    asm volatile("cp.async.cg.shared.global [%0], [%1], 16;"
                 :: "r"(saddr), "l"(g));
}

// ---------------- fp32 -> fp16 convert ----------------
__global__ __launch_bounds__(256) void f2h_kernel(
    const float* __restrict__ in, __half* __restrict__ out)
{
    int i = blockIdx.x * 256 + threadIdx.x;
    float4 v = ((const float4*)in)[i];
    __half2 h0 = __floats2half2_rn(v.x, v.y);
    __half2 h1 = __floats2half2_rn(v.z, v.w);
    ((__half2*)out)[i * 2]     = h0;
    ((__half2*)out)[i * 2 + 1] = h1;
}

// ------------- weight transpose -> fp16: Wt[n*1024+k] = W(k,n) -------------
__global__ __launch_bounds__(256) void wtr_kernel(
    const float* __restrict__ W, __half* __restrict__ Wt,
    int ldb, long bstride, int GRPs)
{
    __shared__ float ts[32][33];
    const int k0 = blockIdx.x * 32, n0 = blockIdx.y * 32;
    const int tx = threadIdx.x & 31, ty = threadIdx.x >> 5;
    const int mask = (1 << GRPs) - 1;
#pragma unroll
    for (int j = 0; j < 4; j++) {
        int k = k0 + ty + j * 8;
        int n = n0 + tx;
        ts[ty + j * 8][tx] =
            W[((long)(n >> GRPs)) * bstride + (long)k * ldb + (n & mask)];
    }
    __syncthreads();
#pragma unroll
    for (int j = 0; j < 4; j++) {
        int n = n0 + ty + j * 8;
        Wt[(long)n * 1024 + k0 + tx] = __float2half(ts[tx][ty + j * 8]);
    }
}

// ====== fp16 mma.sync GEMM: cp.async + swizzled smem + ldmatrix ======
// A half [M][1024], Wt half n-major [N][1024]. 128x128 tile, BK=64, 3 stages.
__global__ __launch_bounds__(256) void gemm_h(
    const __half* __restrict__ A, const __half* __restrict__ Wt,
    float* __restrict__ C, __half* __restrict__ Ch,
    const float* __restrict__ bias, const int* __restrict__ lens, int relu)
{
    extern __shared__ char smh[];
    const uint32_t smemBase = smem_u32(smh);
    const int tid = threadIdx.x;
    const int wid = tid >> 5, lane = tid & 31;
    const int warpm = wid >> 2, warpn = wid & 3;
    const int m0 = blockIdx.x * 128;
    const int n0 = blockIdx.y * 128;

    float acc[4][4][4];
#pragma unroll
    for (int mi = 0; mi < 4; mi++)
#pragma unroll
        for (int ni = 0; ni < 4; ni++)
#pragma unroll
            for (int c = 0; c < 4; c++) acc[mi][ni][c] = 0.f;

    // stage: A 16KB (128 rows x 128B) + B 16KB. 8 chunks/row, XOR swizzle.
    auto load_stage = [&](int slot, int k0) {
        uint32_t sb = smemBase + slot * 32768;
#pragma unroll
        for (int i = 0; i < 4; i++) {
            int m = (tid >> 3) + i * 32;
            int c = tid & 7;
            uint32_t off = (uint32_t)(m * 128 + ((c ^ (m & 7)) * 16));
            cp16(sb + off,         A  + (long)(m0 + m) * GK + k0 + c * 8);
            cp16(sb + 16384 + off, Wt + (long)(n0 + m) * GK + k0 + c * 8);
        }
        asm volatile("cp.async.commit_group;" ::: "memory");
    };

    auto compute_stage = [&](int slot) {
        const uint32_t sA = smemBase + slot * 32768;
        const uint32_t sB = sA + 16384;
#pragma unroll
        for (int ks = 0; ks < 4; ks++) {           // 4 x k16 per stage
            uint32_t bfr[2][4];
#pragma unroll
            for (int nip = 0; nip < 2; nip++) {
                int row = warpn * 32 + nip * 16 + (lane & 7)
                        + ((lane >> 4) & 1) * 8;
                int ch = ks * 2 + ((lane >> 3) & 1);
                ldsm_x4(bfr[nip], sB + (uint32_t)(row * 128
                         + ((ch ^ (row & 7)) * 16)));
            }
#pragma unroll
            for (int mi = 0; mi < 4; mi++) {
                int row = warpm * 64 + mi * 16 + (lane & 7)
                        + ((lane >> 3) & 1) * 8;
                int ch = ks * 2 + (lane >> 4);
                uint32_t af[4];
                ldsm_x4(af, sA + (uint32_t)(row * 128
                         + ((ch ^ (row & 7)) * 16)));
#pragma unroll
                for (int ni = 0; ni < 4; ni++)
                    mma_f16(acc[mi][ni], af, bfr[ni >> 1] + (ni & 1) * 2);
            }
        }
    };

    load_stage(0, 0);
    load_stage(1, BKH);
    asm volatile("cp.async.wait_group 1;" ::: "memory");
    __syncthreads();

    for (int it = 0; it < NITH; it++) {
        compute_stage(it % NST);
        if (it + 2 < NITH) {
            load_stage((it + 2) % NST, (it + 2) * BKH);
            asm volatile("cp.async.wait_group 1;" ::: "memory");
        } else {
            asm volatile("cp.async.wait_group 0;" ::: "memory");
        }
        __syncthreads();
    }

    // ---- epilogue ----
    const int g = lane >> 2, t2 = (lane & 3) * 2;
#pragma unroll
    for (int mi = 0; mi < 4; mi++) {
        int mA = m0 + warpm * 64 + mi * 16 + g;
        int mB = mA + 8;
        bool vA = (mA & 1023) < lens[mA >> 10];
        bool vB = (mB & 1023) < lens[mB >> 10];
#pragma unroll
        for (int ni = 0; ni < 4; ni++) {
            int nn = n0 + warpn * 32 + ni * 8 + t2;
            float bx = 0.f, by = 0.f;
            if (bias) { float2 bv = *(const float2*)(bias + nn); bx = bv.x; by = bv.y; }
            float2 rA, rB;
            rA.x = acc[mi][ni][0] + bx; rA.y = acc[mi][ni][1] + by;
            rB.x = acc[mi][ni][2] + bx; rB.y = acc[mi][ni][3] + by;
            if (relu) {
                rA.x = fmaxf(rA.x, 0.f); rA.y = fmaxf(rA.y, 0.f);
                rB.x = fmaxf(rB.x, 0.f); rB.y = fmaxf(rB.y, 0.f);
            }
            if (!vA) { rA.x = 0.f; rA.y = 0.f; }
            if (!vB) { rB.x = 0.f; rB.y = 0.f; }
            if (C) {
                *(float2*)(C + (long)mA * Eq + nn) = rA;
                *(float2*)(C + (long)mB * Eq + nn) = rB;
            }
            if (Ch) {
                *(__half2*)(Ch + (long)mA * Eq + nn) = __floats2half2_rn(rA.x, rA.y);
                *(__half2*)(Ch + (long)mB * Eq + nn) = __floats2half2_rn(rB.x, rB.y);
            }
        }
    }
}

// ============ flash attention on mma.sync tf32 (Br=64, Bc=64, d=64) ============
__global__ __launch_bounds__(128) void flash_mma(
    const float* __restrict__ Q, const float* __restrict__ K,
    const float* __restrict__ V, float* __restrict__ O,
    const int* __restrict__ lens, int causal)
{
    extern __shared__ float fsm[];
    float* KF = fsm;
    float* VF = fsm + 4096;
    uint32_t* PF = (uint32_t*)(fsm + 8192);

    const int tid = threadIdx.x;
    const int w = tid >> 5, lane = tid & 31;
    const int g = lane >> 2, t = lane & 3;
    const int bh = blockIdx.y, b = bh >> 4, h = bh & 15;
    const int q0 = blockIdx.x * 64;
    const int len = lens[b];

    const long headBase = (long)(b * Lq) * Eq + h * DKq;
    const int ig0 = q0 + w * 16 + g;
    const int ig1 = ig0 + 8;

    uint32_t qf[8][4];
    {
        const float* qp = Q + headBase;
#pragma unroll
        for (int ks = 0; ks < 8; ks++) {
            int c = ks * 8 + t;
            qf[ks][0] = f2tf32(qp[(long)ig0 * Eq + c]);
            qf[ks][1] = f2tf32(qp[(long)ig1 * Eq + c]);
            qf[ks][2] = f2tf32(qp[(long)ig0 * Eq + c + 4]);
            qf[ks][3] = f2tf32(qp[(long)ig1 * Eq + c + 4]);
        }
    }

    float of[8][4];
#pragma unroll
    for (int nd = 0; nd < 8; nd++) {
        of[nd][0] = 0.f; of[nd][1] = 0.f; of[nd][2] = 0.f; of[nd][3] = 0.f;
    }
    float m0 = -INFINITY, m1 = -INFINITY, l0 = 0.f, l1 = 0.f;

    const int kend = (q0 >= len) ? 0 : (causal ? min(len, q0 + 64) : len);
    uint32_t* pfw = PF + w * 1024;

    for (int k0 = 0; k0 < kend; k0 += 64) {
        const long baseK = (long)(b * Lq + k0) * Eq + h * DKq;
#pragma unroll
        for (int i = 0; i < 8; i++) {
            int idx = tid + i * 128;
            int j = idx >> 4, d4 = (idx & 15) * 4;
            long gi = baseK + (long)j * Eq + d4;
            float4 kv = *(const float4*)(K + gi);
            uint32_t* pk = (uint32_t*)&KF[((j >> 3) * 8 + (d4 >> 3)) * 64
                                          + ((j & 7) * 4) * 2 + ((d4 & 4) ? 1 : 0)];
            pk[0] = f2tf32(kv.x); pk[2] = f2tf32(kv.y);
            pk[4] = f2tf32(kv.z); pk[6] = f2tf32(kv.w);
            float4 vv = *(const float4*)(V + gi);
            uint32_t* pv = (uint32_t*)&VF[((d4 >> 3) * 8 + (j >> 3)) * 64
                                          + ((d4 & 7) * 4 + (j & 3)) * 2
                                          + ((j & 4) ? 1 : 0)];
            pv[0] = f2tf32(vv.x); pv[8] = f2tf32(vv.y);
            pv[16] = f2tf32(vv.z); pv[24] = f2tf32(vv.w);
        }
        __syncthreads();

        float sf[8][4];
#pragma unroll
        for (int nj = 0; nj < 8; nj++) {
            sf[nj][0] = 0.f; sf[nj][1] = 0.f; sf[nj][2] = 0.f; sf[nj][3] = 0.f;
#pragma unroll
            for (int ks = 0; ks < 8; ks++) {
                uint32_t bf[2];
                *(uint2*)bf = *(const uint2*)&KF[(nj * 8 + ks) * 64 + lane * 2];
                mma_tf32(sf[nj], qf[ks], bf);
            }
        }

        const bool needLen  = (k0 + 64 > len);
        const bool needDiag = causal && (k0 + 64 > q0);
        if (needLen || needDiag) {
#pragma unroll
            for (int nj = 0; nj < 8; nj++) {
                int jg0 = k0 + nj * 8 + 2 * t, jg1 = jg0 + 1;
                float a00 = (jg0 >= len ? NEGV : 0.f)
                          + (needDiag && jg0 > ig0 ? NEGV : 0.f);
                float a01 = (jg1 >= len ? NEGV : 0.f)
                          + (needDiag && jg1 > ig0 ? NEGV : 0.f);
                float a10 = (jg0 >= len ? NEGV : 0.f)
                          + (needDiag && jg0 > ig1 ? NEGV : 0.f);
                float a11 = (jg1 >= len ? NEGV : 0.f)
                          + (needDiag && jg1 > ig1 ? NEGV : 0.f);
                sf[nj][0] = (sf[nj][0] + a00) * SCALEV;
                sf[nj][1] = (sf[nj][1] + a01) * SCALEV;
                sf[nj][2] = (sf[nj][2] + a10) * SCALEV;
                sf[nj][3] = (sf[nj][3] + a11) * SCALEV;
            }
        } else {
#pragma unroll
            for (int nj = 0; nj < 8; nj++) {
                sf[nj][0] *= SCALEV; sf[nj][1] *= SCALEV;
                sf[nj][2] *= SCALEV; sf[nj][3] *= SCALEV;
            }
        }

        float rm0 = -INFINITY, rm1 = -INFINITY;
#pragma unroll
        for (int nj = 0; nj < 8; nj++) {
            rm0 = fmaxf(rm0, fmaxf(sf[nj][0], sf[nj][1]));
            rm1 = fmaxf(rm1, fmaxf(sf[nj][2], sf[nj][3]));
        }
        rm0 = fmaxf(rm0, __shfl_xor_sync(0xffffffffu, rm0, 1));
        rm0 = fmaxf(rm0, __shfl_xor_sync(0xffffffffu, rm0, 2));
        rm1 = fmaxf(rm1, __shfl_xor_sync(0xffffffffu, rm1, 1));
        rm1 = fmaxf(rm1, __shfl_xor_sync(0xffffffffu, rm1, 2));

        float nm0 = fmaxf(m0, rm0), nm1 = fmaxf(m1, rm1);
        float al0 = __expf(m0 - nm0), al1 = __expf(m1 - nm1);
        m0 = nm0; m1 = nm1;

        float rs0 = 0.f, rs1 = 0.f;
        const int lA = (g * 4 + ((2 * t) & 3)) * 4 + ((t >= 2) ? 2 : 0);
        const int lB = (g * 4 + ((2 * t + 1) & 3)) * 4 + ((t >= 2) ? 2 : 0);
#pragma unroll
        for (int nj = 0; nj < 8; nj++) {
            float p00 = __expf(sf[nj][0] - nm0);
            float p01 = __expf(sf[nj][1] - nm0);
            float p10 = __expf(sf[nj][2] - nm1);
            float p11 = __expf(sf[nj][3] - nm1);
            rs0 += p00 + p01;
            rs1 += p10 + p11;
            pfw[nj * 128 + lA]     = f2tf32(p00);
            pfw[nj * 128 + lA + 1] = f2tf32(p10);
            pfw[nj * 128 + lB]     = f2tf32(p01);
            pfw[nj * 128 + lB + 1] = f2tf32(p11);
        }
        rs0 += __shfl_xor_sync(0xffffffffu, rs0, 1);
        rs0 += __shfl_xor_sync(0xffffffffu, rs0, 2);
        rs1 += __shfl_xor_sync(0xffffffffu, rs1, 1);
        rs1 += __shfl_xor_sync(0xffffffffu, rs1, 2);
        l0 = l0 * al0 + rs0;
        l1 = l1 * al1 + rs1;

#pragma unroll
        for (int nd = 0; nd < 8; nd++) {
            of[nd][0] *= al0; of[nd][1] *= al0;
            of[nd][2] *= al1; of[nd][3] *= al1;
        }
        __syncwarp();

#pragma unroll
        for (int kj = 0; kj < 8; kj++) {
            uint32_t af[4];
            *(uint4*)af = *(const uint4*)&pfw[kj * 128 + lane * 4];
#pragma unroll
            for (int nd = 0; nd < 8; nd++) {
                uint32_t bf[2];
                *(uint2*)bf = *(const uint2*)&VF[(nd * 8 + kj) * 64 + lane * 2];
                mma_tf32(of[nd], af, bf);
            }
        }
        __syncthreads();
    }

    const bool v0 = ig0 < len, v1 = ig1 < len;
    const float inv0 = v0 ? (1.f / l0) : 0.f;
    const float inv1 = v1 ? (1.f / l1) : 0.f;
    float* op = O + headBase;
#pragma unroll
    for (int nd = 0; nd < 8; nd++) {
        int c = nd * 8 + 2 * t;
        float2 r0v, r1v;
        r0v.x = of[nd][0] * inv0; r0v.y = of[nd][1] * inv0;
        r1v.x = of[nd][2] * inv1; r1v.y = of[nd][3] * inv1;
        *(float2*)(op + (long)ig0 * Eq + c) = r0v;
        *(float2*)(op + (long)ig1 * Eq + c) = r1v;
    }
}

// ------------ fused residual + layernorm (optional fp16 copy out) ------------
__global__ __launch_bounds__(256) void ln_kernel(
    const float* __restrict__ A, const float* __restrict__ Z,
    const float* __restrict__ g, const float* __restrict__ bb,
    float* __restrict__ out, __half* __restrict__ outh)
{
    __shared__ float sred[8], ssred[8];
    const int row = blockIdx.x, tid = threadIdx.x;
    const float4* a4 = (const float4*)(A + (long)row * Eq);
    const float4* z4 = (const float4*)(Z + (long)row * Eq);
    float4 av = a4[tid], zv = z4[tid];
    float4 t = make_float4(av.x+zv.x, av.y+zv.y, av.z+zv.z, av.w+zv.w);
    float s  = t.x + t.y + t.z + t.w;
    float ss = t.x*t.x + t.y*t.y + t.z*t.z + t.w*t.w;
#pragma unroll
    for (int o2 = 16; o2 > 0; o2 >>= 1) {
        s  += __shfl_xor_sync(0xffffffffu, s,  o2);
        ss += __shfl_xor_sync(0xffffffffu, ss, o2);
    }
    int wid = tid >> 5, lane = tid & 31;
    if (lane == 0) { sred[wid] = s; ssred[wid] = ss; }
    __syncthreads();
    if (tid < 8) {
        s = sred[tid]; ss = ssred[tid];
#pragma unroll
        for (int o2 = 4; o2 > 0; o2 >>= 1) {
            s  += __shfl_xor_sync(0xffu, s,  o2);
            ss += __shfl_xor_sync(0xffu, ss, o2);
        }
        if (tid == 0) { sred[0] = s; ssred[0] = ss; }
    }
    __syncthreads();
    const float mu  = sred[0] * (1.f / Eq);
    const float var = ssred[0] * (1.f / Eq) - mu * mu;
    const float rinv = rsqrtf(var + 1e-5f);
    float4 gv = ((const float4*)g)[tid];
    float4 bv = ((const float4*)bb)[tid];
    float4 r;
    r.x = (t.x - mu) * rinv * gv.x + bv.x;
    r.y = (t.y - mu) * rinv * gv.y + bv.y;
    r.z = (t.z - mu) * rinv * gv.z + bv.z;
    r.w = (t.w - mu) * rinv * gv.w + bv.w;
    ((float4*)(out + (long)row * Eq))[tid] = r;
    if (outh) {
        __half2* oh = (__half2*)(outh + (long)row * Eq);
        oh[tid * 2]     = __floats2half2_rn(r.x, r.y);
        oh[tid * 2 + 1] = __floats2half2_rn(r.z, r.w);
    }
}

// ---------------- launch ----------------
extern "C" void kernel_launch(void* const* d_in, const int* in_sizes, int n_in,
                              void* d_out, int out_size)
{
    const float* x    = (const float*)d_in[0];
    const float* ctx  = (const float*)d_in[1];
    const int*   lens = (const int*)  d_in[2];
    const float* Wq1  = (const float*)d_in[4];
    const float* Wk1  = (const float*)d_in[5];
    const float* Wv1  = (const float*)d_in[6];
    const float* Wq2  = (const float*)d_in[7];
    const float* Wk2  = (const float*)d_in[8];
    const float* Wv2  = (const float*)d_in[9];
    const float* ln1g = (const float*)d_in[10];
    const float* ln1b = (const float*)d_in[11];
    const float* ln2g = (const float*)d_in[12];
    const float* ln2b = (const float*)d_in[13];
    const float* ln3g = (const float*)d_in[14];
    const float* ln3b = (const float*)d_in[15];
    const float* fc1w = (const float*)d_in[16];
    const float* fc1b = (const float*)d_in[17];
    const float* fc2w = (const float*)d_in[18];
    const float* fc2b = (const float*)d_in[19];
    float* out = (float*)d_out;

    float *Qb, *Kb, *Vb, *Zb, *X1, *X2;
    __half *xh, *ctxh, *X1h, *X2h, *Hbh, *Wt;
    cudaGetSymbolAddress((void**)&Qb, g_Q);
    cudaGetSymbolAddress((void**)&Kb, g_K);
    cudaGetSymbolAddress((void**)&Vb, g_V);
    cudaGetSymbolAddress((void**)&Zb, g_Z);
    cudaGetSymbolAddress((void**)&X1, g_X1);
    cudaGetSymbolAddress((void**)&X2, g_X2);
    cudaGetSymbolAddress((void**)&xh,   g_xh);
    cudaGetSymbolAddress((void**)&ctxh, g_ctxh);
    cudaGetSymbolAddress((void**)&X1h,  g_X1h);
    cudaGetSymbolAddress((void**)&X2h,  g_X2h);
    cudaGetSymbolAddress((void**)&Hbh,  g_Hbh);
    cudaGetSymbolAddress((void**)&Wt,   g_Wt);
#define WT(i) (Wt + (size_t)(i) * 1048576u)

    const int SMEM_G = NST * 32768;    // 96 KB for gemm
    const int SMEM_F = 12288 * 4;      // 48 KB for flash
    cudaFuncSetAttribute(gemm_h, cudaFuncAttributeMaxDynamicSharedMemorySize,
                         SMEM_G);
    cudaFuncSetAttribute(flash_mma, cudaFuncAttributeMaxDynamicSharedMemorySize,
                         SMEM_F);

    // fp16 conversions of GEMM A-inputs
    f2h_kernel<<<Mq*Eq/1024, 256>>>(x,   xh);
    f2h_kernel<<<Mq*Eq/1024, 256>>>(ctx, ctxh);

    dim3 tg(32, 32);
    const long PSTRIDE = (long)Eq * DKq;
    wtr_kernel<<<tg, 256>>>(Wq1,  WT(0), DKq, PSTRIDE, 6);
    wtr_kernel<<<tg, 256>>>(Wk1,  WT(1), DKq, PSTRIDE, 6);
    wtr_kernel<<<tg, 256>>>(Wv1,  WT(2), DKq, PSTRIDE, 6);
    wtr_kernel<<<tg, 256>>>(Wq2,  WT(3), DKq, PSTRIDE, 6);
    wtr_kernel<<<tg, 256>>>(Wk2,  WT(4), DKq, PSTRIDE, 6);
    wtr_kernel<<<tg, 256>>>(Wv2,  WT(5), DKq, PSTRIDE, 6);
    wtr_kernel<<<tg, 256>>>(fc1w, WT(6), Eq,  0L,      10);
    wtr_kernel<<<tg, 256>>>(fc2w, WT(7), Eq,  0L,      10);

    dim3 gg(Mq/128, Eq/128);         // 64 x 8
    dim3 fg(Lq/64, Bq*Hq);           // 16 x 128

    // --- self attention ---
    gemm_h<<<gg, 256, SMEM_G>>>(xh, WT(0), Qb, nullptr, nullptr, lens, 0);
    gemm_h<<<gg, 256, SMEM_G>>>(xh, WT(1), Kb, nullptr, nullptr, lens, 0);
    gemm_h<<<gg, 256, SMEM_G>>>(xh, WT(2), Vb, nullptr, nullptr, lens, 0);
    flash_mma<<<fg, 128, SMEM_F>>>(Qb, Kb, Vb, Zb, lens, 1);
    ln_kernel<<<Mq, 256>>>(x, Zb, ln1g, ln1b, X1, X1h);

    // --- cross attention (Q,K from context; V from x1) ---
    gemm_h<<<gg, 256, SMEM_G>>>(ctxh, WT(3), Qb, nullptr, nullptr, lens, 0);
    gemm_h<<<gg, 256, SMEM_G>>>(ctxh, WT(4), Kb, nullptr, nullptr, lens, 0);
    gemm_h<<<gg, 256, SMEM_G>>>(X1h,  WT(5), Vb, nullptr, nullptr, lens, 0);
    flash_mma<<<fg, 128, SMEM_F>>>(Qb, Kb, Vb, Zb, lens, 0);
    ln_kernel<<<Mq, 256>>>(X1, Zb, ln2g, ln2b, X2, X2h);

    // --- FFN ---
    gemm_h<<<gg, 256, SMEM_G>>>(X2h, WT(6), nullptr, Hbh, fc1b, lens, 1);
    gemm_h<<<gg, 256, SMEM_G>>>(Hbh, WT(7), Zb, nullptr, fc2b, lens, 0);
    ln_kernel<<<Mq, 256>>>(X2, Zb, ln3g, ln3b, out, nullptr);
}

// round 9
// speedup vs baseline: 10.2432x; 1.4202x over previous
#include <cuda_runtime.h>
#include <cuda_fp16.h>
#include <math.h>
#include <stdint.h>

#define Bq   8
#define Lq   1024
#define Eq   1024
#define Hq   16
#define DKq  64
#define Mq   (Bq*Lq)
#define NEGV (-1000000000.0f)
#define SCALEV 0.125f

#define GK   1024
#define BKH  64
#define NITH (GK / BKH)
#define NST  3

// ---------------- scratch (no cudaMalloc allowed) ----------------
__device__ float  g_Z [Mq*Eq];
__device__ float  g_X1[Mq*Eq];
__device__ float  g_X2[Mq*Eq];
__device__ __half g_Qh  [Mq*Eq];
__device__ __half g_Kh  [Mq*Eq];
__device__ __half g_Vh  [Mq*Eq];
__device__ __half g_xh  [Mq*Eq];
__device__ __half g_ctxh[Mq*Eq];
__device__ __half g_X1h [Mq*Eq];
__device__ __half g_X2h [Mq*Eq];
__device__ __half g_Hbh [Mq*Eq];
__device__ __half g_Wt  [8u * 1024u * 1024u];

__device__ __forceinline__ uint32_t smem_u32(const void* p) {
    uint32_t a;
    asm("{ .reg .u64 t; cvta.to.shared.u64 t, %1; cvt.u32.u64 %0, t; }"
        : "=r"(a) : "l"(p));
    return a;
}
__device__ __forceinline__ uint32_t packh2(float a, float b) {
    __half2 h = __floats2half2_rn(a, b);
    return *(uint32_t*)&h;
}
__device__ __forceinline__ void mma_f16(float* c, const uint32_t* a,
                                        const uint32_t* b) {
    asm volatile(
        "mma.sync.aligned.m16n8k16.row.col.f32.f16.f16.f32 "
        "{%0,%1,%2,%3}, {%4,%5,%6,%7}, {%8,%9}, {%0,%1,%2,%3};"
        : "+f"(c[0]), "+f"(c[1]), "+f"(c[2]), "+f"(c[3])
        : "r"(a[0]), "r"(a[1]), "r"(a[2]), "r"(a[3]), "r"(b[0]), "r"(b[1]));
}
__device__ __forceinline__ void ldsm_x4(uint32_t* r, uint32_t addr) {
    asm volatile("ldmatrix.sync.aligned.m8n8.x4.shared.b16 {%0,%1,%2,%3}, [%4];"
        : "=r"(r[0]), "=r"(r[1]), "=r"(r[2]), "=r"(r[3]) : "r"(addr));
}
__device__ __forceinline__ void ldsm_x4t(uint32_t* r, uint32_t addr) {
    asm volatile("ldmatrix.sync.aligned.m8n8.x4.trans.shared.b16 {%0,%1,%2,%3}, [%4];"
        : "=r"(r[0]), "=r"(r[1]), "=r"(r[2]), "=r"(r[3]) : "r"(addr));
}
__device__ __forceinline__ void cp16(uint32_t saddr, const void* g) {
    asm volatile("cp.async.cg.shared.global [%0], [%1], 16;"
                 :: "r"(saddr), "l"(g));
}

// ---------------- fp32 -> fp16 convert ----------------
__global__ __launch_bounds__(256) void f2h_kernel(
    const float* __restrict__ in, __half* __restrict__ out)
{
    int i = blockIdx.x * 256 + threadIdx.x;
    float4 v = ((const float4*)in)[i];
    ((__half2*)out)[i * 2]     = __floats2half2_rn(v.x, v.y);
    ((__half2*)out)[i * 2 + 1] = __floats2half2_rn(v.z, v.w);
}

// ------------- weight transpose -> fp16: Wt[n*1024+k] = W(k,n) -------------
__global__ __launch_bounds__(256) void wtr_kernel(
    const float* __restrict__ W, __half* __restrict__ Wt,
    int ldb, long bstride, int GRPs)
{
    __shared__ float ts[32][33];
    const int k0 = blockIdx.x * 32, n0 = blockIdx.y * 32;
    const int tx = threadIdx.x & 31, ty = threadIdx.x >> 5;
    const int mask = (1 << GRPs) - 1;
#pragma unroll
    for (int j = 0; j < 4; j++) {
        int k = k0 + ty + j * 8;
        int n = n0 + tx;
        ts[ty + j * 8][tx] =
            W[((long)(n >> GRPs)) * bstride + (long)k * ldb + (n & mask)];
    }
    __syncthreads();
#pragma unroll
    for (int j = 0; j < 4; j++) {
        int n = n0 + ty + j * 8;
        Wt[(long)n * 1024 + k0 + tx] = __float2half(ts[tx][ty + j * 8]);
    }
}

// ====== fp16 mma.sync GEMM: cp.async + swizzled smem + ldmatrix ======
__global__ __launch_bounds__(256) void gemm_h(
    const __half* __restrict__ A, const __half* __restrict__ Wt,
    float* __restrict__ C, __half* __restrict__ Ch,
    const float* __restrict__ bias, const int* __restrict__ lens, int relu)
{
    extern __shared__ char smh[];
    const uint32_t smemBase = smem_u32(smh);
    const int tid = threadIdx.x;
    const int wid = tid >> 5, lane = tid & 31;
    const int warpm = wid >> 2, warpn = wid & 3;
    const int m0 = blockIdx.x * 128;
    const int n0 = blockIdx.y * 128;

    float acc[4][4][4];
#pragma unroll
    for (int mi = 0; mi < 4; mi++)
#pragma unroll
        for (int ni = 0; ni < 4; ni++)
#pragma unroll
            for (int c = 0; c < 4; c++) acc[mi][ni][c] = 0.f;

    auto load_stage = [&](int slot, int k0) {
        uint32_t sb = smemBase + slot * 32768;
#pragma unroll
        for (int i = 0; i < 4; i++) {
            int m = (tid >> 3) + i * 32;
            int c = tid & 7;
            uint32_t off = (uint32_t)(m * 128 + ((c ^ (m & 7)) * 16));
            cp16(sb + off,         A  + (long)(m0 + m) * GK + k0 + c * 8);
            cp16(sb + 16384 + off, Wt + (long)(n0 + m) * GK + k0 + c * 8);
        }
        asm volatile("cp.async.commit_group;" ::: "memory");
    };

    auto compute_stage = [&](int slot) {
        const uint32_t sA = smemBase + slot * 32768;
        const uint32_t sB = sA + 16384;
#pragma unroll
        for (int ks = 0; ks < 4; ks++) {
            uint32_t bfr[2][4];
#pragma unroll
            for (int nip = 0; nip < 2; nip++) {
                int row = warpn * 32 + nip * 16 + (lane & 7)
                        + ((lane >> 4) & 1) * 8;
                int ch = ks * 2 + ((lane >> 3) & 1);
                ldsm_x4(bfr[nip], sB + (uint32_t)(row * 128
                         + ((ch ^ (row & 7)) * 16)));
            }
#pragma unroll
            for (int mi = 0; mi < 4; mi++) {
                int row = warpm * 64 + mi * 16 + (lane & 7)
                        + ((lane >> 3) & 1) * 8;
                int ch = ks * 2 + (lane >> 4);
                uint32_t af[4];
                ldsm_x4(af, sA + (uint32_t)(row * 128
                         + ((ch ^ (row & 7)) * 16)));
#pragma unroll
                for (int ni = 0; ni < 4; ni++)
                    mma_f16(acc[mi][ni], af, bfr[ni >> 1] + (ni & 1) * 2);
            }
        }
    };

    load_stage(0, 0);
    load_stage(1, BKH);
    asm volatile("cp.async.wait_group 1;" ::: "memory");
    __syncthreads();

    for (int it = 0; it < NITH; it++) {
        compute_stage(it % NST);
        if (it + 2 < NITH) {
            load_stage((it + 2) % NST, (it + 2) * BKH);
            asm volatile("cp.async.wait_group 1;" ::: "memory");
        } else {
            asm volatile("cp.async.wait_group 0;" ::: "memory");
        }
        __syncthreads();
    }

    const int g = lane >> 2, t2 = (lane & 3) * 2;
#pragma unroll
    for (int mi = 0; mi < 4; mi++) {
        int mA = m0 + warpm * 64 + mi * 16 + g;
        int mB = mA + 8;
        bool vA = (mA & 1023) < lens[mA >> 10];
        bool vB = (mB & 1023) < lens[mB >> 10];
#pragma unroll
        for (int ni = 0; ni < 4; ni++) {
            int nn = n0 + warpn * 32 + ni * 8 + t2;
            float bx = 0.f, by = 0.f;
            if (bias) { float2 bv = *(const float2*)(bias + nn); bx = bv.x; by = bv.y; }
            float2 rA, rB;
            rA.x = acc[mi][ni][0] + bx; rA.y = acc[mi][ni][1] + by;
            rB.x = acc[mi][ni][2] + bx; rB.y = acc[mi][ni][3] + by;
            if (relu) {
                rA.x = fmaxf(rA.x, 0.f); rA.y = fmaxf(rA.y, 0.f);
                rB.x = fmaxf(rB.x, 0.f); rB.y = fmaxf(rB.y, 0.f);
            }
            if (!vA) { rA.x = 0.f; rA.y = 0.f; }
            if (!vB) { rB.x = 0.f; rB.y = 0.f; }
            if (C) {
                *(float2*)(C + (long)mA * Eq + nn) = rA;
                *(float2*)(C + (long)mB * Eq + nn) = rB;
            }
            if (Ch) {
                *(__half2*)(Ch + (long)mA * Eq + nn) = __floats2half2_rn(rA.x, rA.y);
                *(__half2*)(Ch + (long)mB * Eq + nn) = __floats2half2_rn(rB.x, rB.y);
            }
        }
    }
}

// ====== flash attention, fp16 mma (Br=64, Bc=64, d=64), cp.async K/V ======
// smem: Q 8KB @0; stage s (s=0..2): K 8KB @ 8192+s*16384, V 8KB @ +8192.
__global__ __launch_bounds__(128) void flash_h(
    const __half* __restrict__ Q, const __half* __restrict__ K,
    const __half* __restrict__ V, float* __restrict__ O,
    const int* __restrict__ lens, int causal)
{
    extern __shared__ char fsmh[];
    const uint32_t smemBase = smem_u32(fsmh);
    const int tid = threadIdx.x;
    const int w = tid >> 5, lane = tid & 31;
    const int g = lane >> 2, t = lane & 3;
    const int bh = blockIdx.y, b = bh >> 4, h = bh & 15;
    const int q0 = blockIdx.x * 64;
    const int len = lens[b];

    const long headBase = (long)(b * Lq) * Eq + h * DKq;
    const int ig0 = q0 + w * 16 + g;
    const int ig1 = ig0 + 8;

    float of[8][4];
#pragma unroll
    for (int nd = 0; nd < 8; nd++) {
        of[nd][0] = 0.f; of[nd][1] = 0.f; of[nd][2] = 0.f; of[nd][3] = 0.f;
    }
    float m0 = -INFINITY, m1 = -INFINITY, l0 = 0.f, l1 = 0.f;

    const int kend = (q0 >= len) ? 0 : (causal ? min(len, q0 + 64) : len);
    const int ntiles = (kend + 63) >> 6;

    auto load_kv = [&](int slot, int j0) {
        uint32_t sb = smemBase + 8192 + slot * 16384;
        const __half* Kp = K + headBase + (long)j0 * Eq;
        const __half* Vp = V + headBase + (long)j0 * Eq;
#pragma unroll
        for (int i = 0; i < 4; i++) {
            int idx = tid + i * 128;          // 0..511
            int r = idx >> 3, c = idx & 7;
            uint32_t off = (uint32_t)(r * 128 + ((c ^ (r & 7)) * 16));
            cp16(sb + off,        Kp + (long)r * Eq + c * 8);
            cp16(sb + 8192 + off, Vp + (long)r * Eq + c * 8);
        }
        asm volatile("cp.async.commit_group;" ::: "memory");
    };

    if (ntiles > 0) {
        // stage Q tile (64 x 128B) + first K/V
        {
            const __half* Qp = Q + headBase + (long)q0 * Eq;
#pragma unroll
            for (int i = 0; i < 4; i++) {
                int idx = tid + i * 128;
                int r = idx >> 3, c = idx & 7;
                uint32_t off = (uint32_t)(r * 128 + ((c ^ (r & 7)) * 16));
                cp16(smemBase + off, Qp + (long)r * Eq + c * 8);
            }
        }
        load_kv(0, 0);
        if (ntiles > 1) {
            load_kv(1, 64);
            asm volatile("cp.async.wait_group 1;" ::: "memory");
        } else {
            asm volatile("cp.async.wait_group 0;" ::: "memory");
        }
        __syncthreads();

        // Q A-fragments from smem
        uint32_t qf[4][4];
        {
            int row = w * 16 + (lane & 7) + ((lane >> 3) & 1) * 8;
#pragma unroll
            for (int ks = 0; ks < 4; ks++) {
                int ch = ks * 2 + (lane >> 4);
                ldsm_x4(qf[ks], smemBase + (uint32_t)(row * 128
                         + ((ch ^ (row & 7)) * 16)));
            }
        }

        for (int kt = 0; kt < ntiles; kt++) {
            const int k0 = kt * 64;
            const uint32_t sK = smemBase + 8192 + (kt % NST) * 16384;
            const uint32_t sV = sK + 8192;

            // ---- S = Q K^T (fp16 mma) ----
            float sf[8][4];
#pragma unroll
            for (int nj = 0; nj < 8; nj++) {
                sf[nj][0] = 0.f; sf[nj][1] = 0.f;
                sf[nj][2] = 0.f; sf[nj][3] = 0.f;
            }
#pragma unroll
            for (int ks = 0; ks < 4; ks++) {
#pragma unroll
                for (int nb = 0; nb < 4; nb++) {
                    int row = nb * 16 + (lane & 7) + ((lane >> 4) & 1) * 8;
                    int ch = ks * 2 + ((lane >> 3) & 1);
                    uint32_t bfr[4];
                    ldsm_x4(bfr, sK + (uint32_t)(row * 128
                             + ((ch ^ (row & 7)) * 16)));
                    mma_f16(sf[nb * 2],     qf[ks], bfr);
                    mma_f16(sf[nb * 2 + 1], qf[ks], bfr + 2);
                }
            }

            // ---- masks + scale ----
            const bool needLen  = (k0 + 64 > len);
            const bool needDiag = causal && (k0 + 64 > q0);
            if (needLen || needDiag) {
#pragma unroll
                for (int nj = 0; nj < 8; nj++) {
                    int jg0 = k0 + nj * 8 + 2 * t, jg1 = jg0 + 1;
                    float a00 = (jg0 >= len ? NEGV : 0.f)
                              + (needDiag && jg0 > ig0 ? NEGV : 0.f);
                    float a01 = (jg1 >= len ? NEGV : 0.f)
                              + (needDiag && jg1 > ig0 ? NEGV : 0.f);
                    float a10 = (jg0 >= len ? NEGV : 0.f)
                              + (needDiag && jg0 > ig1 ? NEGV : 0.f);
                    float a11 = (jg1 >= len ? NEGV : 0.f)
                              + (needDiag && jg1 > ig1 ? NEGV : 0.f);
                    sf[nj][0] = (sf[nj][0] + a00) * SCALEV;
                    sf[nj][1] = (sf[nj][1] + a01) * SCALEV;
                    sf[nj][2] = (sf[nj][2] + a10) * SCALEV;
                    sf[nj][3] = (sf[nj][3] + a11) * SCALEV;
                }
            } else {
#pragma unroll
                for (int nj = 0; nj < 8; nj++) {
                    sf[nj][0] *= SCALEV; sf[nj][1] *= SCALEV;
                    sf[nj][2] *= SCALEV; sf[nj][3] *= SCALEV;
                }
            }

            // ---- online softmax (quad-replicated row state) ----
            float rm0 = -INFINITY, rm1 = -INFINITY;
#pragma unroll
            for (int nj = 0; nj < 8; nj++) {
                rm0 = fmaxf(rm0, fmaxf(sf[nj][0], sf[nj][1]));
                rm1 = fmaxf(rm1, fmaxf(sf[nj][2], sf[nj][3]));
            }
            rm0 = fmaxf(rm0, __shfl_xor_sync(0xffffffffu, rm0, 1));
            rm0 = fmaxf(rm0, __shfl_xor_sync(0xffffffffu, rm0, 2));
            rm1 = fmaxf(rm1, __shfl_xor_sync(0xffffffffu, rm1, 1));
            rm1 = fmaxf(rm1, __shfl_xor_sync(0xffffffffu, rm1, 2));

            float nm0 = fmaxf(m0, rm0), nm1 = fmaxf(m1, rm1);
            float al0 = __expf(m0 - nm0), al1 = __expf(m1 - nm1);
            m0 = nm0; m1 = nm1;

            float rs0 = 0.f, rs1 = 0.f;
#pragma unroll
            for (int nj = 0; nj < 8; nj++) {
                sf[nj][0] = __expf(sf[nj][0] - nm0);
                sf[nj][1] = __expf(sf[nj][1] - nm0);
                sf[nj][2] = __expf(sf[nj][2] - nm1);
                sf[nj][3] = __expf(sf[nj][3] - nm1);
                rs0 += sf[nj][0] + sf[nj][1];
                rs1 += sf[nj][2] + sf[nj][3];
            }
            rs0 += __shfl_xor_sync(0xffffffffu, rs0, 1);
            rs0 += __shfl_xor_sync(0xffffffffu, rs0, 2);
            rs1 += __shfl_xor_sync(0xffffffffu, rs1, 1);
            rs1 += __shfl_xor_sync(0xffffffffu, rs1, 2);
            l0 = l0 * al0 + rs0;
            l1 = l1 * al1 + rs1;

#pragma unroll
            for (int nd = 0; nd < 8; nd++) {
                of[nd][0] *= al0; of[nd][1] *= al0;
                of[nd][2] *= al1; of[nd][3] *= al1;
            }

            // ---- O += P V : P packed straight from registers ----
#pragma unroll
            for (int kj = 0; kj < 4; kj++) {
                uint32_t pa[4];
                pa[0] = packh2(sf[2 * kj][0],     sf[2 * kj][1]);
                pa[1] = packh2(sf[2 * kj][2],     sf[2 * kj][3]);
                pa[2] = packh2(sf[2 * kj + 1][0], sf[2 * kj + 1][1]);
                pa[3] = packh2(sf[2 * kj + 1][2], sf[2 * kj + 1][3]);
                int row = kj * 16 + (lane & 7) + ((lane >> 3) & 1) * 8;
#pragma unroll
                for (int ndp = 0; ndp < 4; ndp++) {
                    int ch = ndp * 2 + (lane >> 4);
                    uint32_t vb[4];
                    ldsm_x4t(vb, sV + (uint32_t)(row * 128
                              + ((ch ^ (row & 7)) * 16)));
                    mma_f16(of[ndp * 2],     pa, vb);
                    mma_f16(of[ndp * 2 + 1], pa, vb + 2);
                }
            }

            if (kt + 2 < ntiles) {
                load_kv((kt + 2) % NST, (kt + 2) * 64);
                asm volatile("cp.async.wait_group 1;" ::: "memory");
            } else {
                asm volatile("cp.async.wait_group 0;" ::: "memory");
            }
            __syncthreads();
        }
    }

    // ---- epilogue ----
    const bool v0 = ig0 < len, v1 = ig1 < len;
    const float inv0 = v0 ? (1.f / l0) : 0.f;
    const float inv1 = v1 ? (1.f / l1) : 0.f;
    float* op = O + headBase;
#pragma unroll
    for (int nd = 0; nd < 8; nd++) {
        int c = nd * 8 + 2 * t;
        float2 r0v, r1v;
        r0v.x = of[nd][0] * inv0; r0v.y = of[nd][1] * inv0;
        r1v.x = of[nd][2] * inv1; r1v.y = of[nd][3] * inv1;
        *(float2*)(op + (long)ig0 * Eq + c) = r0v;
        *(float2*)(op + (long)ig1 * Eq + c) = r1v;
    }
}

// ------------ fused residual + layernorm (optional fp16 copy out) ------------
__global__ __launch_bounds__(256) void ln_kernel(
    const float* __restrict__ A, const float* __restrict__ Z,
    const float* __restrict__ g, const float* __restrict__ bb,
    float* __restrict__ out, __half* __restrict__ outh)
{
    __shared__ float sred[8], ssred[8];
    const int row = blockIdx.x, tid = threadIdx.x;
    const float4* a4 = (const float4*)(A + (long)row * Eq);
    const float4* z4 = (const float4*)(Z + (long)row * Eq);
    float4 av = a4[tid], zv = z4[tid];
    float4 t = make_float4(av.x+zv.x, av.y+zv.y, av.z+zv.z, av.w+zv.w);
    float s  = t.x + t.y + t.z + t.w;
    float ss = t.x*t.x + t.y*t.y + t.z*t.z + t.w*t.w;
#pragma unroll
    for (int o2 = 16; o2 > 0; o2 >>= 1) {
        s  += __shfl_xor_sync(0xffffffffu, s,  o2);
        ss += __shfl_xor_sync(0xffffffffu, ss, o2);
    }
    int wid = tid >> 5, lane = tid & 31;
    if (lane == 0) { sred[wid] = s; ssred[wid] = ss; }
    __syncthreads();
    if (tid < 8) {
        s = sred[tid]; ss = ssred[tid];
#pragma unroll
        for (int o2 = 4; o2 > 0; o2 >>= 1) {
            s  += __shfl_xor_sync(0xffu, s,  o2);
            ss += __shfl_xor_sync(0xffu, ss, o2);
        }
        if (tid == 0) { sred[0] = s; ssred[0] = ss; }
    }
    __syncthreads();
    const float mu  = sred[0] * (1.f / Eq);
    const float var = ssred[0] * (1.f / Eq) - mu * mu;
    const float rinv = rsqrtf(var + 1e-5f);
    float4 gv = ((const float4*)g)[tid];
    float4 bv = ((const float4*)bb)[tid];
    float4 r;
    r.x = (t.x - mu) * rinv * gv.x + bv.x;
    r.y = (t.y - mu) * rinv * gv.y + bv.y;
    r.z = (t.z - mu) * rinv * gv.z + bv.z;
    r.w = (t.w - mu) * rinv * gv.w + bv.w;
    ((float4*)(out + (long)row * Eq))[tid] = r;
    if (outh) {
        __half2* oh = (__half2*)(outh + (long)row * Eq);
        oh[tid * 2]     = __floats2half2_rn(r.x, r.y);
        oh[tid * 2 + 1] = __floats2half2_rn(r.z, r.w);
    }
}

// ---------------- launch ----------------
extern "C" void kernel_launch(void* const* d_in, const int* in_sizes, int n_in,
                              void* d_out, int out_size)
{
    const float* x    = (const float*)d_in[0];
    const float* ctx  = (const float*)d_in[1];
    const int*   lens = (const int*)  d_in[2];
    const float* Wq1  = (const float*)d_in[4];
    const float* Wk1  = (const float*)d_in[5];
    const float* Wv1  = (const float*)d_in[6];
    const float* Wq2  = (const float*)d_in[7];
    const float* Wk2  = (const float*)d_in[8];
    const float* Wv2  = (const float*)d_in[9];
    const float* ln1g = (const float*)d_in[10];
    const float* ln1b = (const float*)d_in[11];
    const float* ln2g = (const float*)d_in[12];
    const float* ln2b = (const float*)d_in[13];
    const float* ln3g = (const float*)d_in[14];
    const float* ln3b = (const float*)d_in[15];
    const float* fc1w = (const float*)d_in[16];
    const float* fc1b = (const float*)d_in[17];
    const float* fc2w = (const float*)d_in[18];
    const float* fc2b = (const float*)d_in[19];
    float* out = (float*)d_out;

    float *Zb, *X1, *X2;
    __half *Qh, *Kh, *Vh, *xh, *ctxh, *X1h, *X2h, *Hbh, *Wt;
    cudaGetSymbolAddress((void**)&Zb, g_Z);
    cudaGetSymbolAddress((void**)&X1, g_X1);
    cudaGetSymbolAddress((void**)&X2, g_X2);
    cudaGetSymbolAddress((void**)&Qh,   g_Qh);
    cudaGetSymbolAddress((void**)&Kh,   g_Kh);
    cudaGetSymbolAddress((void**)&Vh,   g_Vh);
    cudaGetSymbolAddress((void**)&xh,   g_xh);
    cudaGetSymbolAddress((void**)&ctxh, g_ctxh);
    cudaGetSymbolAddress((void**)&X1h,  g_X1h);
    cudaGetSymbolAddress((void**)&X2h,  g_X2h);
    cudaGetSymbolAddress((void**)&Hbh,  g_Hbh);
    cudaGetSymbolAddress((void**)&Wt,   g_Wt);
#define WT(i) (Wt + (size_t)(i) * 1048576u)

    const int SMEM_G = NST * 32768;            // 96 KB gemm
    const int SMEM_F = 8192 + NST * 16384;     // 56 KB flash
    cudaFuncSetAttribute(gemm_h, cudaFuncAttributeMaxDynamicSharedMemorySize,
                         SMEM_G);
    cudaFuncSetAttribute(flash_h, cudaFuncAttributeMaxDynamicSharedMemorySize,
                         SMEM_F);

    f2h_kernel<<<Mq*Eq/1024, 256>>>(x,   xh);
    f2h_kernel<<<Mq*Eq/1024, 256>>>(ctx, ctxh);

    dim3 tg(32, 32);
    const long PSTRIDE = (long)Eq * DKq;
    wtr_kernel<<<tg, 256>>>(Wq1,  WT(0), DKq, PSTRIDE, 6);
    wtr_kernel<<<tg, 256>>>(Wk1,  WT(1), DKq, PSTRIDE, 6);
    wtr_kernel<<<tg, 256>>>(Wv1,  WT(2), DKq, PSTRIDE, 6);
    wtr_kernel<<<tg, 256>>>(Wq2,  WT(3), DKq, PSTRIDE, 6);
    wtr_kernel<<<tg, 256>>>(Wk2,  WT(4), DKq, PSTRIDE, 6);
    wtr_kernel<<<tg, 256>>>(Wv2,  WT(5), DKq, PSTRIDE, 6);
    wtr_kernel<<<tg, 256>>>(fc1w, WT(6), Eq,  0L,      10);
    wtr_kernel<<<tg, 256>>>(fc2w, WT(7), Eq,  0L,      10);

    dim3 gg(Mq/128, Eq/128);         // 64 x 8
    dim3 fg(Lq/64, Bq*Hq);           // 16 x 128

    // --- self attention ---
    gemm_h<<<gg, 256, SMEM_G>>>(xh, WT(0), nullptr, Qh, nullptr, lens, 0);
    gemm_h<<<gg, 256, SMEM_G>>>(xh, WT(1), nullptr, Kh, nullptr, lens, 0);
    gemm_h<<<gg, 256, SMEM_G>>>(xh, WT(2), nullptr, Vh, nullptr, lens, 0);
    flash_h<<<fg, 128, SMEM_F>>>(Qh, Kh, Vh, Zb, lens, 1);
    ln_kernel<<<Mq, 256>>>(x, Zb, ln1g, ln1b, X1, X1h);

    // --- cross attention (Q,K from context; V from x1) ---
    gemm_h<<<gg, 256, SMEM_G>>>(ctxh, WT(3), nullptr, Qh, nullptr, lens, 0);
    gemm_h<<<gg, 256, SMEM_G>>>(ctxh, WT(4), nullptr, Kh, nullptr, lens, 0);
    gemm_h<<<gg, 256, SMEM_G>>>(X1h,  WT(5), nullptr, Vh, nullptr, lens, 0);
    flash_h<<<fg, 128, SMEM_F>>>(Qh, Kh, Vh, Zb, lens, 0);
    ln_kernel<<<Mq, 256>>>(X1, Zb, ln2g, ln2b, X2, X2h);

    // --- FFN ---
    gemm_h<<<gg, 256, SMEM_G>>>(X2h, WT(6), nullptr, Hbh, fc1b, lens, 1);
    gemm_h<<<gg, 256, SMEM_G>>>(Hbh, WT(7), Zb, nullptr, fc2b, lens, 0);
    ln_kernel<<<Mq, 256>>>(X2, Zb, ln3g, ln3b, out, nullptr);
}

// round 10
// speedup vs baseline: 10.7445x; 1.0489x over previous
#include <cuda_runtime.h>
#include <cuda_fp16.h>
#include <math.h>
#include <stdint.h>

#define Bq   8
#define Lq   1024
#define Eq   1024
#define Hq   16
#define DKq  64
#define Mq   (Bq*Lq)
#define NEGV (-1000000000.0f)
#define SCALEV 0.125f

#define GK   1024
#define BKH  64
#define NITH (GK / BKH)
#define NST  3

// ---------------- scratch (no cudaMalloc allowed) ----------------
__device__ float  g_Z [Mq*Eq];
__device__ float  g_X1[Mq*Eq];
__device__ float  g_X2[Mq*Eq];
__device__ __half g_Qh  [Mq*Eq];
__device__ __half g_Kh  [Mq*Eq];
__device__ __half g_Vh  [Mq*Eq];
__device__ __half g_Q2h [Mq*Eq];
__device__ __half g_K2h [Mq*Eq];
__device__ __half g_xh  [Mq*Eq];
__device__ __half g_ctxh[Mq*Eq];
__device__ __half g_X1h [Mq*Eq];
__device__ __half g_X2h [Mq*Eq];
__device__ __half g_Hbh [Mq*Eq];
__device__ __half g_Wt  [8u * 1024u * 1024u];

__device__ __forceinline__ uint32_t smem_u32(const void* p) {
    uint32_t a;
    asm("{ .reg .u64 t; cvta.to.shared.u64 t, %1; cvt.u32.u64 %0, t; }"
        : "=r"(a) : "l"(p));
    return a;
}
__device__ __forceinline__ uint32_t packh2(float a, float b) {
    __half2 h = __floats2half2_rn(a, b);
    return *(uint32_t*)&h;
}
__device__ __forceinline__ void mma_f16(float* c, const uint32_t* a,
                                        const uint32_t* b) {
    asm volatile(
        "mma.sync.aligned.m16n8k16.row.col.f32.f16.f16.f32 "
        "{%0,%1,%2,%3}, {%4,%5,%6,%7}, {%8,%9}, {%0,%1,%2,%3};"
        : "+f"(c[0]), "+f"(c[1]), "+f"(c[2]), "+f"(c[3])
        : "r"(a[0]), "r"(a[1]), "r"(a[2]), "r"(a[3]), "r"(b[0]), "r"(b[1]));
}
__device__ __forceinline__ void ldsm_x4(uint32_t* r, uint32_t addr) {
    asm volatile("ldmatrix.sync.aligned.m8n8.x4.shared.b16 {%0,%1,%2,%3}, [%4];"
        : "=r"(r[0]), "=r"(r[1]), "=r"(r[2]), "=r"(r[3]) : "r"(addr));
}
__device__ __forceinline__ void ldsm_x4t(uint32_t* r, uint32_t addr) {
    asm volatile("ldmatrix.sync.aligned.m8n8.x4.trans.shared.b16 {%0,%1,%2,%3}, [%4];"
        : "=r"(r[0]), "=r"(r[1]), "=r"(r[2]), "=r"(r[3]) : "r"(addr));
}
__device__ __forceinline__ void cp16(uint32_t saddr, const void* g) {
    asm volatile("cp.async.cg.shared.global [%0], [%1], 16;"
                 :: "r"(saddr), "l"(g));
}

// ---------------- batched fp32 -> fp16 convert ----------------
struct F2hArgs { const float* in[2]; __half* out[2]; };
__global__ __launch_bounds__(256) void f2h_batch(F2hArgs a)
{
    const float* in = a.in[blockIdx.y];
    __half* out = a.out[blockIdx.y];
    int i = blockIdx.x * 256 + threadIdx.x;
    float4 v = ((const float4*)in)[i];
    ((__half2*)out)[i * 2]     = __floats2half2_rn(v.x, v.y);
    ((__half2*)out)[i * 2 + 1] = __floats2half2_rn(v.z, v.w);
}

// ------------- batched weight transpose -> fp16 -------------
struct WtrArgs { const float* W[8]; int ldb[8]; long bstride[8]; int GRPs[8]; };
__global__ __launch_bounds__(256) void wtr_batch(WtrArgs a, __half* WtBase)
{
    __shared__ float ts[32][33];
    const int z = blockIdx.z;
    const float* W = a.W[z];
    __half* Wt = WtBase + (size_t)z * 1048576u;
    const int ldb = a.ldb[z];
    const long bstride = a.bstride[z];
    const int mask = (1 << a.GRPs[z]) - 1;
    const int GRPs = a.GRPs[z];
    const int k0 = blockIdx.x * 32, n0 = blockIdx.y * 32;
    const int tx = threadIdx.x & 31, ty = threadIdx.x >> 5;
#pragma unroll
    for (int j = 0; j < 4; j++) {
        int k = k0 + ty + j * 8;
        int n = n0 + tx;
        ts[ty + j * 8][tx] =
            W[((long)(n >> GRPs)) * bstride + (long)k * ldb + (n & mask)];
    }
    __syncthreads();
#pragma unroll
    for (int j = 0; j < 4; j++) {
        int n = n0 + ty + j * 8;
        Wt[(long)n * 1024 + k0 + tx] = __float2half(ts[tx][ty + j * 8]);
    }
}

// ====== fp16 mma.sync GEMM core: cp.async + swizzled smem + ldmatrix ======
__device__ __forceinline__ void gemm_core(
    const __half* __restrict__ A, const __half* __restrict__ Wt,
    float* __restrict__ C, __half* __restrict__ Ch,
    const float* __restrict__ bias, const int* __restrict__ lens, int relu,
    char* smh)
{
    const uint32_t smemBase = smem_u32(smh);
    const int tid = threadIdx.x;
    const int wid = tid >> 5, lane = tid & 31;
    const int warpm = wid >> 2, warpn = wid & 3;
    const int m0 = blockIdx.x * 128;
    const int n0 = blockIdx.y * 128;

    float acc[4][4][4];
#pragma unroll
    for (int mi = 0; mi < 4; mi++)
#pragma unroll
        for (int ni = 0; ni < 4; ni++)
#pragma unroll
            for (int c = 0; c < 4; c++) acc[mi][ni][c] = 0.f;

    auto load_stage = [&](int slot, int k0) {
        uint32_t sb = smemBase + slot * 32768;
#pragma unroll
        for (int i = 0; i < 4; i++) {
            int m = (tid >> 3) + i * 32;
            int c = tid & 7;
            uint32_t off = (uint32_t)(m * 128 + ((c ^ (m & 7)) * 16));
            cp16(sb + off,         A  + (long)(m0 + m) * GK + k0 + c * 8);
            cp16(sb + 16384 + off, Wt + (long)(n0 + m) * GK + k0 + c * 8);
        }
        asm volatile("cp.async.commit_group;" ::: "memory");
    };

    auto compute_stage = [&](int slot) {
        const uint32_t sA = smemBase + slot * 32768;
        const uint32_t sB = sA + 16384;
#pragma unroll
        for (int ks = 0; ks < 4; ks++) {
            uint32_t bfr[2][4];
#pragma unroll
            for (int nip = 0; nip < 2; nip++) {
                int row = warpn * 32 + nip * 16 + (lane & 7)
                        + ((lane >> 4) & 1) * 8;
                int ch = ks * 2 + ((lane >> 3) & 1);
                ldsm_x4(bfr[nip], sB + (uint32_t)(row * 128
                         + ((ch ^ (row & 7)) * 16)));
            }
#pragma unroll
            for (int mi = 0; mi < 4; mi++) {
                int row = warpm * 64 + mi * 16 + (lane & 7)
                        + ((lane >> 3) & 1) * 8;
                int ch = ks * 2 + (lane >> 4);
                uint32_t af[4];
                ldsm_x4(af, sA + (uint32_t)(row * 128
                         + ((ch ^ (row & 7)) * 16)));
#pragma unroll
                for (int ni = 0; ni < 4; ni++)
                    mma_f16(acc[mi][ni], af, bfr[ni >> 1] + (ni & 1) * 2);
            }
        }
    };

    load_stage(0, 0);
    load_stage(1, BKH);
    asm volatile("cp.async.wait_group 1;" ::: "memory");
    __syncthreads();

    for (int it = 0; it < NITH; it++) {
        compute_stage(it % NST);
        if (it + 2 < NITH) {
            load_stage((it + 2) % NST, (it + 2) * BKH);
            asm volatile("cp.async.wait_group 1;" ::: "memory");
        } else {
            asm volatile("cp.async.wait_group 0;" ::: "memory");
        }
        __syncthreads();
    }

    const int g = lane >> 2, t2 = (lane & 3) * 2;
#pragma unroll
    for (int mi = 0; mi < 4; mi++) {
        int mA = m0 + warpm * 64 + mi * 16 + g;
        int mB = mA + 8;
        bool vA = (mA & 1023) < lens[mA >> 10];
        bool vB = (mB & 1023) < lens[mB >> 10];
#pragma unroll
        for (int ni = 0; ni < 4; ni++) {
            int nn = n0 + warpn * 32 + ni * 8 + t2;
            float bx = 0.f, by = 0.f;
            if (bias) { float2 bv = *(const float2*)(bias + nn); bx = bv.x; by = bv.y; }
            float2 rA, rB;
            rA.x = acc[mi][ni][0] + bx; rA.y = acc[mi][ni][1] + by;
            rB.x = acc[mi][ni][2] + bx; rB.y = acc[mi][ni][3] + by;
            if (relu) {
                rA.x = fmaxf(rA.x, 0.f); rA.y = fmaxf(rA.y, 0.f);
                rB.x = fmaxf(rB.x, 0.f); rB.y = fmaxf(rB.y, 0.f);
            }
            if (!vA) { rA.x = 0.f; rA.y = 0.f; }
            if (!vB) { rB.x = 0.f; rB.y = 0.f; }
            if (C) {
                *(float2*)(C + (long)mA * Eq + nn) = rA;
                *(float2*)(C + (long)mB * Eq + nn) = rB;
            }
            if (Ch) {
                *(__half2*)(Ch + (long)mA * Eq + nn) = __floats2half2_rn(rA.x, rA.y);
                *(__half2*)(Ch + (long)mB * Eq + nn) = __floats2half2_rn(rB.x, rB.y);
            }
        }
    }
}

// batched projection GEMMs (no bias, no relu, half out)
struct Gemm5Args { const __half* A[5]; const __half* W[5]; __half* Ch[5]; };
__global__ __launch_bounds__(256) void gemm_batch5(
    Gemm5Args a, const int* __restrict__ lens)
{
    extern __shared__ char smh[];
    const int z = blockIdx.z;
    gemm_core(a.A[z], a.W[z], nullptr, a.Ch[z], nullptr, lens, 0, smh);
}

__global__ __launch_bounds__(256) void gemm_h(
    const __half* __restrict__ A, const __half* __restrict__ Wt,
    float* __restrict__ C, __half* __restrict__ Ch,
    const float* __restrict__ bias, const int* __restrict__ lens, int relu)
{
    extern __shared__ char smh[];
    gemm_core(A, Wt, C, Ch, bias, lens, relu, smh);
}

// ====== flash attention, fp16 mma (Br=64, Bc=64, d=64), cp.async K/V ======
__global__ __launch_bounds__(128) void flash_h(
    const __half* __restrict__ Q, const __half* __restrict__ K,
    const __half* __restrict__ V, float* __restrict__ O,
    const int* __restrict__ lens, int causal)
{
    extern __shared__ char fsmh[];
    const uint32_t smemBase = smem_u32(fsmh);
    const int tid = threadIdx.x;
    const int w = tid >> 5, lane = tid & 31;
    const int g = lane >> 2, t = lane & 3;
    const int bh = blockIdx.y, b = bh >> 4, h = bh & 15;
    const int q0 = blockIdx.x * 64;
    const int len = lens[b];

    const long headBase = (long)(b * Lq) * Eq + h * DKq;
    const int ig0 = q0 + w * 16 + g;
    const int ig1 = ig0 + 8;

    float of[8][4];
#pragma unroll
    for (int nd = 0; nd < 8; nd++) {
        of[nd][0] = 0.f; of[nd][1] = 0.f; of[nd][2] = 0.f; of[nd][3] = 0.f;
    }
    float m0 = -INFINITY, m1 = -INFINITY, l0 = 0.f, l1 = 0.f;

    const int kend = (q0 >= len) ? 0 : (causal ? min(len, q0 + 64) : len);
    const int ntiles = (kend + 63) >> 6;

    auto load_kv = [&](int slot, int j0) {
        uint32_t sb = smemBase + 8192 + slot * 16384;
        const __half* Kp = K + headBase + (long)j0 * Eq;
        const __half* Vp = V + headBase + (long)j0 * Eq;
#pragma unroll
        for (int i = 0; i < 4; i++) {
            int idx = tid + i * 128;
            int r = idx >> 3, c = idx & 7;
            uint32_t off = (uint32_t)(r * 128 + ((c ^ (r & 7)) * 16));
            cp16(sb + off,        Kp + (long)r * Eq + c * 8);
            cp16(sb + 8192 + off, Vp + (long)r * Eq + c * 8);
        }
        asm volatile("cp.async.commit_group;" ::: "memory");
    };

    if (ntiles > 0) {
        {
            const __half* Qp = Q + headBase + (long)q0 * Eq;
#pragma unroll
            for (int i = 0; i < 4; i++) {
                int idx = tid + i * 128;
                int r = idx >> 3, c = idx & 7;
                uint32_t off = (uint32_t)(r * 128 + ((c ^ (r & 7)) * 16));
                cp16(smemBase + off, Qp + (long)r * Eq + c * 8);
            }
        }
        load_kv(0, 0);
        if (ntiles > 1) {
            load_kv(1, 64);
            asm volatile("cp.async.wait_group 1;" ::: "memory");
        } else {
            asm volatile("cp.async.wait_group 0;" ::: "memory");
        }
        __syncthreads();

        uint32_t qf[4][4];
        {
            int row = w * 16 + (lane & 7) + ((lane >> 3) & 1) * 8;
#pragma unroll
            for (int ks = 0; ks < 4; ks++) {
                int ch = ks * 2 + (lane >> 4);
                ldsm_x4(qf[ks], smemBase + (uint32_t)(row * 128
                         + ((ch ^ (row & 7)) * 16)));
            }
        }

        for (int kt = 0; kt < ntiles; kt++) {
            const int k0 = kt * 64;
            const uint32_t sK = smemBase + 8192 + (kt % NST) * 16384;
            const uint32_t sV = sK + 8192;

            float sf[8][4];
#pragma unroll
            for (int nj = 0; nj < 8; nj++) {
                sf[nj][0] = 0.f; sf[nj][1] = 0.f;
                sf[nj][2] = 0.f; sf[nj][3] = 0.f;
            }
#pragma unroll
            for (int ks = 0; ks < 4; ks++) {
#pragma unroll
                for (int nb = 0; nb < 4; nb++) {
                    int row = nb * 16 + (lane & 7) + ((lane >> 4) & 1) * 8;
                    int ch = ks * 2 + ((lane >> 3) & 1);
                    uint32_t bfr[4];
                    ldsm_x4(bfr, sK + (uint32_t)(row * 128
                             + ((ch ^ (row & 7)) * 16)));
                    mma_f16(sf[nb * 2],     qf[ks], bfr);
                    mma_f16(sf[nb * 2 + 1], qf[ks], bfr + 2);
                }
            }

            const bool needLen  = (k0 + 64 > len);
            const bool needDiag = causal && (k0 + 64 > q0);
            if (needLen || needDiag) {
#pragma unroll
                for (int nj = 0; nj < 8; nj++) {
                    int jg0 = k0 + nj * 8 + 2 * t, jg1 = jg0 + 1;
                    float a00 = (jg0 >= len ? NEGV : 0.f)
                              + (needDiag && jg0 > ig0 ? NEGV : 0.f);
                    float a01 = (jg1 >= len ? NEGV : 0.f)
                              + (needDiag && jg1 > ig0 ? NEGV : 0.f);
                    float a10 = (jg0 >= len ? NEGV : 0.f)
                              + (needDiag && jg0 > ig1 ? NEGV : 0.f);
                    float a11 = (jg1 >= len ? NEGV : 0.f)
                              + (needDiag && jg1 > ig1 ? NEGV : 0.f);
                    sf[nj][0] = (sf[nj][0] + a00) * SCALEV;
                    sf[nj][1] = (sf[nj][1] + a01) * SCALEV;
                    sf[nj][2] = (sf[nj][2] + a10) * SCALEV;
                    sf[nj][3] = (sf[nj][3] + a11) * SCALEV;
                }
            } else {
#pragma unroll
                for (int nj = 0; nj < 8; nj++) {
                    sf[nj][0] *= SCALEV; sf[nj][1] *= SCALEV;
                    sf[nj][2] *= SCALEV; sf[nj][3] *= SCALEV;
                }
            }

            float rm0 = -INFINITY, rm1 = -INFINITY;
#pragma unroll
            for (int nj = 0; nj < 8; nj++) {
                rm0 = fmaxf(rm0, fmaxf(sf[nj][0], sf[nj][1]));
                rm1 = fmaxf(rm1, fmaxf(sf[nj][2], sf[nj][3]));
            }
            rm0 = fmaxf(rm0, __shfl_xor_sync(0xffffffffu, rm0, 1));
            rm0 = fmaxf(rm0, __shfl_xor_sync(0xffffffffu, rm0, 2));
            rm1 = fmaxf(rm1, __shfl_xor_sync(0xffffffffu, rm1, 1));
            rm1 = fmaxf(rm1, __shfl_xor_sync(0xffffffffu, rm1, 2));

            float nm0 = fmaxf(m0, rm0), nm1 = fmaxf(m1, rm1);
            float al0 = __expf(m0 - nm0), al1 = __expf(m1 - nm1);
            m0 = nm0; m1 = nm1;

            float rs0 = 0.f, rs1 = 0.f;
#pragma unroll
            for (int nj = 0; nj < 8; nj++) {
                sf[nj][0] = __expf(sf[nj][0] - nm0);
                sf[nj][1] = __expf(sf[nj][1] - nm0);
                sf[nj][2] = __expf(sf[nj][2] - nm1);
                sf[nj][3] = __expf(sf[nj][3] - nm1);
                rs0 += sf[nj][0] + sf[nj][1];
                rs1 += sf[nj][2] + sf[nj][3];
            }
            rs0 += __shfl_xor_sync(0xffffffffu, rs0, 1);
            rs0 += __shfl_xor_sync(0xffffffffu, rs0, 2);
            rs1 += __shfl_xor_sync(0xffffffffu, rs1, 1);
            rs1 += __shfl_xor_sync(0xffffffffu, rs1, 2);
            l0 = l0 * al0 + rs0;
            l1 = l1 * al1 + rs1;

#pragma unroll
            for (int nd = 0; nd < 8; nd++) {
                of[nd][0] *= al0; of[nd][1] *= al0;
                of[nd][2] *= al1; of[nd][3] *= al1;
            }

#pragma unroll
            for (int kj = 0; kj < 4; kj++) {
                uint32_t pa[4];
                pa[0] = packh2(sf[2 * kj][0],     sf[2 * kj][1]);
                pa[1] = packh2(sf[2 * kj][2],     sf[2 * kj][3]);
                pa[2] = packh2(sf[2 * kj + 1][0], sf[2 * kj + 1][1]);
                pa[3] = packh2(sf[2 * kj + 1][2], sf[2 * kj + 1][3]);
                int row = kj * 16 + (lane & 7) + ((lane >> 3) & 1) * 8;
#pragma unroll
                for (int ndp = 0; ndp < 4; ndp++) {
                    int ch = ndp * 2 + (lane >> 4);
                    uint32_t vb[4];
                    ldsm_x4t(vb, sV + (uint32_t)(row * 128
                              + ((ch ^ (row & 7)) * 16)));
                    mma_f16(of[ndp * 2],     pa, vb);
                    mma_f16(of[ndp * 2 + 1], pa, vb + 2);
                }
            }

            if (kt + 2 < ntiles) {
                load_kv((kt + 2) % NST, (kt + 2) * 64);
                asm volatile("cp.async.wait_group 1;" ::: "memory");
            } else {
                asm volatile("cp.async.wait_group 0;" ::: "memory");
            }
            __syncthreads();
        }
    }

    const bool v0 = ig0 < len, v1 = ig1 < len;
    const float inv0 = v0 ? (1.f / l0) : 0.f;
    const float inv1 = v1 ? (1.f / l1) : 0.f;
    float* op = O + headBase;
#pragma unroll
    for (int nd = 0; nd < 8; nd++) {
        int c = nd * 8 + 2 * t;
        float2 r0v, r1v;
        r0v.x = of[nd][0] * inv0; r0v.y = of[nd][1] * inv0;
        r1v.x = of[nd][2] * inv1; r1v.y = of[nd][3] * inv1;
        *(float2*)(op + (long)ig0 * Eq + c) = r0v;
        *(float2*)(op + (long)ig1 * Eq + c) = r1v;
    }
}

// ------------ fused residual + layernorm (optional fp16 copy out) ------------
__global__ __launch_bounds__(256) void ln_kernel(
    const float* __restrict__ A, const float* __restrict__ Z,
    const float* __restrict__ g, const float* __restrict__ bb,
    float* __restrict__ out, __half* __restrict__ outh)
{
    __shared__ float sred[8], ssred[8];
    const int row = blockIdx.x, tid = threadIdx.x;
    const float4* a4 = (const float4*)(A + (long)row * Eq);
    const float4* z4 = (const float4*)(Z + (long)row * Eq);
    float4 av = a4[tid], zv = z4[tid];
    float4 t = make_float4(av.x+zv.x, av.y+zv.y, av.z+zv.z, av.w+zv.w);
    float s  = t.x + t.y + t.z + t.w;
    float ss = t.x*t.x + t.y*t.y + t.z*t.z + t.w*t.w;
#pragma unroll
    for (int o2 = 16; o2 > 0; o2 >>= 1) {
        s  += __shfl_xor_sync(0xffffffffu, s,  o2);
        ss += __shfl_xor_sync(0xffffffffu, ss, o2);
    }
    int wid = tid >> 5, lane = tid & 31;
    if (lane == 0) { sred[wid] = s; ssred[wid] = ss; }
    __syncthreads();
    if (tid < 8) {
        s = sred[tid]; ss = ssred[tid];
#pragma unroll
        for (int o2 = 4; o2 > 0; o2 >>= 1) {
            s  += __shfl_xor_sync(0xffu, s,  o2);
            ss += __shfl_xor_sync(0xffu, ss, o2);
        }
        if (tid == 0) { sred[0] = s; ssred[0] = ss; }
    }
    __syncthreads();
    const float mu  = sred[0] * (1.f / Eq);
    const float var = ssred[0] * (1.f / Eq) - mu * mu;
    const float rinv = rsqrtf(var + 1e-5f);
    float4 gv = ((const float4*)g)[tid];
    float4 bv = ((const float4*)bb)[tid];
    float4 r;
    r.x = (t.x - mu) * rinv * gv.x + bv.x;
    r.y = (t.y - mu) * rinv * gv.y + bv.y;
    r.z = (t.z - mu) * rinv * gv.z + bv.z;
    r.w = (t.w - mu) * rinv * gv.w + bv.w;
    ((float4*)(out + (long)row * Eq))[tid] = r;
    if (outh) {
        __half2* oh = (__half2*)(outh + (long)row * Eq);
        oh[tid * 2]     = __floats2half2_rn(r.x, r.y);
        oh[tid * 2 + 1] = __floats2half2_rn(r.z, r.w);
    }
}

// ---------------- launch ----------------
extern "C" void kernel_launch(void* const* d_in, const int* in_sizes, int n_in,
                              void* d_out, int out_size)
{
    const float* x    = (const float*)d_in[0];
    const float* ctx  = (const float*)d_in[1];
    const int*   lens = (const int*)  d_in[2];
    const float* Wq1  = (const float*)d_in[4];
    const float* Wk1  = (const float*)d_in[5];
    const float* Wv1  = (const float*)d_in[6];
    const float* Wq2  = (const float*)d_in[7];
    const float* Wk2  = (const float*)d_in[8];
    const float* Wv2  = (const float*)d_in[9];
    const float* ln1g = (const float*)d_in[10];
    const float* ln1b = (const float*)d_in[11];
    const float* ln2g = (const float*)d_in[12];
    const float* ln2b = (const float*)d_in[13];
    const float* ln3g = (const float*)d_in[14];
    const float* ln3b = (const float*)d_in[15];
    const float* fc1w = (const float*)d_in[16];
    const float* fc1b = (const float*)d_in[17];
    const float* fc2w = (const float*)d_in[18];
    const float* fc2b = (const float*)d_in[19];
    float* out = (float*)d_out;

    float *Zb, *X1, *X2;
    __half *Qh, *Kh, *Vh, *Q2h, *K2h, *xh, *ctxh, *X1h, *X2h, *Hbh, *Wt;
    cudaGetSymbolAddress((void**)&Zb, g_Z);
    cudaGetSymbolAddress((void**)&X1, g_X1);
    cudaGetSymbolAddress((void**)&X2, g_X2);
    cudaGetSymbolAddress((void**)&Qh,   g_Qh);
    cudaGetSymbolAddress((void**)&Kh,   g_Kh);
    cudaGetSymbolAddress((void**)&Vh,   g_Vh);
    cudaGetSymbolAddress((void**)&Q2h,  g_Q2h);
    cudaGetSymbolAddress((void**)&K2h,  g_K2h);
    cudaGetSymbolAddress((void**)&xh,   g_xh);
    cudaGetSymbolAddress((void**)&ctxh, g_ctxh);
    cudaGetSymbolAddress((void**)&X1h,  g_X1h);
    cudaGetSymbolAddress((void**)&X2h,  g_X2h);
    cudaGetSymbolAddress((void**)&Hbh,  g_Hbh);
    cudaGetSymbolAddress((void**)&Wt,   g_Wt);
#define WT(i) (Wt + (size_t)(i) * 1048576u)

    const int SMEM_G = NST * 32768;            // 96 KB gemm
    const int SMEM_F = 8192 + NST * 16384;     // 56 KB flash
    cudaFuncSetAttribute(gemm_h, cudaFuncAttributeMaxDynamicSharedMemorySize,
                         SMEM_G);
    cudaFuncSetAttribute(gemm_batch5, cudaFuncAttributeMaxDynamicSharedMemorySize,
                         SMEM_G);
    cudaFuncSetAttribute(flash_h, cudaFuncAttributeMaxDynamicSharedMemorySize,
                         SMEM_F);

    // --- prep: conversions + weight transposes (2 launches) ---
    {
        F2hArgs fa;
        fa.in[0] = x;   fa.out[0] = xh;
        fa.in[1] = ctx; fa.out[1] = ctxh;
        f2h_batch<<<dim3(Mq*Eq/1024, 2), 256>>>(fa);
    }
    {
        const long PSTRIDE = (long)Eq * DKq;
        WtrArgs wa;
        const float* ws[8] = {Wq1, Wk1, Wv1, Wq2, Wk2, Wv2, fc1w, fc2w};
        for (int i = 0; i < 8; i++) {
            wa.W[i] = ws[i];
            wa.ldb[i]     = (i < 6) ? DKq : Eq;
            wa.bstride[i] = (i < 6) ? PSTRIDE : 0L;
            wa.GRPs[i]    = (i < 6) ? 6 : 10;
        }
        wtr_batch<<<dim3(32, 32, 8), 256>>>(wa, Wt);
    }

    dim3 gg(Mq/128, Eq/128);         // 64 x 8
    dim3 fg(Lq/64, Bq*Hq);           // 16 x 128

    // --- all 5 context-independent projections in ONE launch ---
    {
        Gemm5Args ga;
        ga.A[0] = xh;   ga.W[0] = WT(0); ga.Ch[0] = Qh;
        ga.A[1] = xh;   ga.W[1] = WT(1); ga.Ch[1] = Kh;
        ga.A[2] = xh;   ga.W[2] = WT(2); ga.Ch[2] = Vh;
        ga.A[3] = ctxh; ga.W[3] = WT(3); ga.Ch[3] = Q2h;
        ga.A[4] = ctxh; ga.W[4] = WT(4); ga.Ch[4] = K2h;
        gemm_batch5<<<dim3(Mq/128, Eq/128, 5), 256, SMEM_G>>>(ga, lens);
    }

    // --- self attention ---
    flash_h<<<fg, 128, SMEM_F>>>(Qh, Kh, Vh, Zb, lens, 1);
    ln_kernel<<<Mq, 256>>>(x, Zb, ln1g, ln1b, X1, X1h);

    // --- cross attention (V from x1; Q,K precomputed from ctx) ---
    gemm_h<<<gg, 256, SMEM_G>>>(X1h, WT(5), nullptr, Vh, nullptr, lens, 0);
    flash_h<<<fg, 128, SMEM_F>>>(Q2h, K2h, Vh, Zb, lens, 0);
    ln_kernel<<<Mq, 256>>>(X1, Zb, ln2g, ln2b, X2, X2h);

    // --- FFN ---
    gemm_h<<<gg, 256, SMEM_G>>>(X2h, WT(6), nullptr, Hbh, fc1b, lens, 1);
    gemm_h<<<gg, 256, SMEM_G>>>(Hbh, WT(7), Zb, nullptr, fc2b, lens, 0);
    ln_kernel<<<Mq, 256>>>(X2, Zb, ln3g, ln3b, out, nullptr);
}

// round 11
// speedup vs baseline: 15.3393x; 1.4276x over previous
#include <cuda_runtime.h>
#include <cuda_fp16.h>
#include <math.h>
#include <stdint.h>

#define Bq   8
#define Lq   1024
#define Eq   1024
#define Hq   16
#define DKq  64
#define Mq   (Bq*Lq)
#define NEGV (-1000000000.0f)
#define SCALEV 0.125f

#define GK   1024
#define BKH  64
#define NITH (GK / BKH)
#define NST  3

// ---------------- scratch (no cudaMalloc allowed) ----------------
__device__ float  g_Z [Mq*Eq];
__device__ float  g_X1[Mq*Eq];
__device__ float  g_X2[Mq*Eq];
__device__ __half g_Qh  [Mq*Eq];
__device__ __half g_Kh  [Mq*Eq];
__device__ __half g_Vh  [Mq*Eq];
__device__ __half g_Q2h [Mq*Eq];
__device__ __half g_K2h [Mq*Eq];
__device__ __half g_xh  [Mq*Eq];
__device__ __half g_ctxh[Mq*Eq];
__device__ __half g_X1h [Mq*Eq];
__device__ __half g_X2h [Mq*Eq];
__device__ __half g_Hbh [Mq*Eq];
__device__ __half g_Wt  [8u * 1024u * 1024u];

__device__ __forceinline__ uint32_t smem_u32(const void* p) {
    uint32_t a;
    asm("{ .reg .u64 t; cvta.to.shared.u64 t, %1; cvt.u32.u64 %0, t; }"
        : "=r"(a) : "l"(p));
    return a;
}
__device__ __forceinline__ uint32_t packh2(float a, float b) {
    __half2 h = __floats2half2_rn(a, b);
    return *(uint32_t*)&h;
}
__device__ __forceinline__ void mma_f16(float* c, const uint32_t* a,
                                        const uint32_t* b) {
    asm volatile(
        "mma.sync.aligned.m16n8k16.row.col.f32.f16.f16.f32 "
        "{%0,%1,%2,%3}, {%4,%5,%6,%7}, {%8,%9}, {%0,%1,%2,%3};"
        : "+f"(c[0]), "+f"(c[1]), "+f"(c[2]), "+f"(c[3])
        : "r"(a[0]), "r"(a[1]), "r"(a[2]), "r"(a[3]), "r"(b[0]), "r"(b[1]));
}
__device__ __forceinline__ void ldsm_x4(uint32_t* r, uint32_t addr) {
    asm volatile("ldmatrix.sync.aligned.m8n8.x4.shared.b16 {%0,%1,%2,%3}, [%4];"
        : "=r"(r[0]), "=r"(r[1]), "=r"(r[2]), "=r"(r[3]) : "r"(addr));
}
__device__ __forceinline__ void ldsm_x4t(uint32_t* r, uint32_t addr) {
    asm volatile("ldmatrix.sync.aligned.m8n8.x4.trans.shared.b16 {%0,%1,%2,%3}, [%4];"
        : "=r"(r[0]), "=r"(r[1]), "=r"(r[2]), "=r"(r[3]) : "r"(addr));
}
__device__ __forceinline__ void cp16(uint32_t saddr, const void* g) {
    asm volatile("cp.async.cg.shared.global [%0], [%1], 16;"
                 :: "r"(saddr), "l"(g));
}

// ---------------- batched fp32 -> fp16 convert ----------------
struct F2hArgs { const float* in[2]; __half* out[2]; };
__global__ __launch_bounds__(256) void f2h_batch(F2hArgs a)
{
    const float* in = a.in[blockIdx.y];
    __half* out = a.out[blockIdx.y];
    int i = blockIdx.x * 256 + threadIdx.x;
    float4 v = ((const float4*)in)[i];
    ((__half2*)out)[i * 2]     = __floats2half2_rn(v.x, v.y);
    ((__half2*)out)[i * 2 + 1] = __floats2half2_rn(v.z, v.w);
}

// ------------- batched weight transpose -> fp16 -------------
struct WtrArgs { const float* W[8]; int ldb[8]; long bstride[8]; int GRPs[8]; };
__global__ __launch_bounds__(256) void wtr_batch(WtrArgs a, __half* WtBase)
{
    __shared__ float ts[32][33];
    const int z = blockIdx.z;
    const float* W = a.W[z];
    __half* Wt = WtBase + (size_t)z * 1048576u;
    const int ldb = a.ldb[z];
    const long bstride = a.bstride[z];
    const int mask = (1 << a.GRPs[z]) - 1;
    const int GRPs = a.GRPs[z];
    const int k0 = blockIdx.x * 32, n0 = blockIdx.y * 32;
    const int tx = threadIdx.x & 31, ty = threadIdx.x >> 5;
#pragma unroll
    for (int j = 0; j < 4; j++) {
        int k = k0 + ty + j * 8;
        int n = n0 + tx;
        ts[ty + j * 8][tx] =
            W[((long)(n >> GRPs)) * bstride + (long)k * ldb + (n & mask)];
    }
    __syncthreads();
#pragma unroll
    for (int j = 0; j < 4; j++) {
        int n = n0 + ty + j * 8;
        Wt[(long)n * 1024 + k0 + tx] = __float2half(ts[tx][ty + j * 8]);
    }
}

// ====== fp16 mma.sync GEMM core: cp.async + swizzled smem + ldmatrix ======
// Skips the whole mainloop when the 128-row M-tile is entirely masked.
__device__ __forceinline__ void gemm_core(
    const __half* __restrict__ A, const __half* __restrict__ Wt,
    float* __restrict__ C, __half* __restrict__ Ch,
    const float* __restrict__ bias, const int* __restrict__ lens, int relu,
    char* smh)
{
    const uint32_t smemBase = smem_u32(smh);
    const int tid = threadIdx.x;
    const int wid = tid >> 5, lane = tid & 31;
    const int warpm = wid >> 2, warpn = wid & 3;
    const int m0 = blockIdx.x * 128;
    const int n0 = blockIdx.y * 128;
    const int tileLen = lens[m0 >> 10];

    float acc[4][4][4];
#pragma unroll
    for (int mi = 0; mi < 4; mi++)
#pragma unroll
        for (int ni = 0; ni < 4; ni++)
#pragma unroll
            for (int c = 0; c < 4; c++) acc[mi][ni][c] = 0.f;

    if ((m0 & 1023) < tileLen) {   // tile has at least one valid row
        auto load_stage = [&](int slot, int k0) {
            uint32_t sb = smemBase + slot * 32768;
#pragma unroll
            for (int i = 0; i < 4; i++) {
                int m = (tid >> 3) + i * 32;
                int c = tid & 7;
                uint32_t off = (uint32_t)(m * 128 + ((c ^ (m & 7)) * 16));
                cp16(sb + off,         A  + (long)(m0 + m) * GK + k0 + c * 8);
                cp16(sb + 16384 + off, Wt + (long)(n0 + m) * GK + k0 + c * 8);
            }
            asm volatile("cp.async.commit_group;" ::: "memory");
        };

        auto compute_stage = [&](int slot) {
            const uint32_t sA = smemBase + slot * 32768;
            const uint32_t sB = sA + 16384;
#pragma unroll
            for (int ks = 0; ks < 4; ks++) {
                uint32_t bfr[2][4];
#pragma unroll
                for (int nip = 0; nip < 2; nip++) {
                    int row = warpn * 32 + nip * 16 + (lane & 7)
                            + ((lane >> 4) & 1) * 8;
                    int ch = ks * 2 + ((lane >> 3) & 1);
                    ldsm_x4(bfr[nip], sB + (uint32_t)(row * 128
                             + ((ch ^ (row & 7)) * 16)));
                }
#pragma unroll
                for (int mi = 0; mi < 4; mi++) {
                    int row = warpm * 64 + mi * 16 + (lane & 7)
                            + ((lane >> 3) & 1) * 8;
                    int ch = ks * 2 + (lane >> 4);
                    uint32_t af[4];
                    ldsm_x4(af, sA + (uint32_t)(row * 128
                             + ((ch ^ (row & 7)) * 16)));
#pragma unroll
                    for (int ni = 0; ni < 4; ni++)
                        mma_f16(acc[mi][ni], af, bfr[ni >> 1] + (ni & 1) * 2);
                }
            }
        };

        load_stage(0, 0);
        load_stage(1, BKH);
        asm volatile("cp.async.wait_group 1;" ::: "memory");
        __syncthreads();

        for (int it = 0; it < NITH; it++) {
            compute_stage(it % NST);
            if (it + 2 < NITH) {
                load_stage((it + 2) % NST, (it + 2) * BKH);
                asm volatile("cp.async.wait_group 1;" ::: "memory");
            } else {
                asm volatile("cp.async.wait_group 0;" ::: "memory");
            }
            __syncthreads();
        }
    }

    const int g = lane >> 2, t2 = (lane & 3) * 2;
#pragma unroll
    for (int mi = 0; mi < 4; mi++) {
        int mA = m0 + warpm * 64 + mi * 16 + g;
        int mB = mA + 8;
        bool vA = (mA & 1023) < tileLen;
        bool vB = (mB & 1023) < tileLen;
#pragma unroll
        for (int ni = 0; ni < 4; ni++) {
            int nn = n0 + warpn * 32 + ni * 8 + t2;
            float bx = 0.f, by = 0.f;
            if (bias) { float2 bv = *(const float2*)(bias + nn); bx = bv.x; by = bv.y; }
            float2 rA, rB;
            rA.x = acc[mi][ni][0] + bx; rA.y = acc[mi][ni][1] + by;
            rB.x = acc[mi][ni][2] + bx; rB.y = acc[mi][ni][3] + by;
            if (relu) {
                rA.x = fmaxf(rA.x, 0.f); rA.y = fmaxf(rA.y, 0.f);
                rB.x = fmaxf(rB.x, 0.f); rB.y = fmaxf(rB.y, 0.f);
            }
            if (!vA) { rA.x = 0.f; rA.y = 0.f; }
            if (!vB) { rB.x = 0.f; rB.y = 0.f; }
            if (C) {
                *(float2*)(C + (long)mA * Eq + nn) = rA;
                *(float2*)(C + (long)mB * Eq + nn) = rB;
            }
            if (Ch) {
                *(__half2*)(Ch + (long)mA * Eq + nn) = __floats2half2_rn(rA.x, rA.y);
                *(__half2*)(Ch + (long)mB * Eq + nn) = __floats2half2_rn(rB.x, rB.y);
            }
        }
    }
}

// batched projection GEMMs (no bias, no relu, half out)
struct Gemm5Args { const __half* A[5]; const __half* W[5]; __half* Ch[5]; };
__global__ __launch_bounds__(256) void gemm_batch5(
    Gemm5Args a, const int* __restrict__ lens)
{
    extern __shared__ char smh[];
    const int z = blockIdx.z;
    gemm_core(a.A[z], a.W[z], nullptr, a.Ch[z], nullptr, lens, 0, smh);
}

__global__ __launch_bounds__(256) void gemm_h(
    const __half* __restrict__ A, const __half* __restrict__ Wt,
    float* __restrict__ C, __half* __restrict__ Ch,
    const float* __restrict__ bias, const int* __restrict__ lens, int relu)
{
    extern __shared__ char smh[];
    gemm_core(A, Wt, C, Ch, bias, lens, relu, smh);
}

// ====== flash attention, fp16 mma (Br=64, Bc=64, d=64), cp.async K/V ======
__global__ __launch_bounds__(128) void flash_h(
    const __half* __restrict__ Q, const __half* __restrict__ K,
    const __half* __restrict__ V, float* __restrict__ O,
    const int* __restrict__ lens, int causal)
{
    extern __shared__ char fsmh[];
    const uint32_t smemBase = smem_u32(fsmh);
    const int tid = threadIdx.x;
    const int w = tid >> 5, lane = tid & 31;
    const int g = lane >> 2, t = lane & 3;
    const int bh = blockIdx.y, b = bh >> 4, h = bh & 15;
    const int q0 = blockIdx.x * 64;
    const int len = lens[b];

    const long headBase = (long)(b * Lq) * Eq + h * DKq;
    const int ig0 = q0 + w * 16 + g;
    const int ig1 = ig0 + 8;

    float of[8][4];
#pragma unroll
    for (int nd = 0; nd < 8; nd++) {
        of[nd][0] = 0.f; of[nd][1] = 0.f; of[nd][2] = 0.f; of[nd][3] = 0.f;
    }
    float m0 = -INFINITY, m1 = -INFINITY, l0 = 0.f, l1 = 0.f;

    const int kend = (q0 >= len) ? 0 : (causal ? min(len, q0 + 64) : len);
    const int ntiles = (kend + 63) >> 6;

    auto load_kv = [&](int slot, int j0) {
        uint32_t sb = smemBase + 8192 + slot * 16384;
        const __half* Kp = K + headBase + (long)j0 * Eq;
        const __half* Vp = V + headBase + (long)j0 * Eq;
#pragma unroll
        for (int i = 0; i < 4; i++) {
            int idx = tid + i * 128;
            int r = idx >> 3, c = idx & 7;
            uint32_t off = (uint32_t)(r * 128 + ((c ^ (r & 7)) * 16));
            cp16(sb + off,        Kp + (long)r * Eq + c * 8);
            cp16(sb + 8192 + off, Vp + (long)r * Eq + c * 8);
        }
        asm volatile("cp.async.commit_group;" ::: "memory");
    };

    if (ntiles > 0) {
        {
            const __half* Qp = Q + headBase + (long)q0 * Eq;
#pragma unroll
            for (int i = 0; i < 4; i++) {
                int idx = tid + i * 128;
                int r = idx >> 3, c = idx & 7;
                uint32_t off = (uint32_t)(r * 128 + ((c ^ (r & 7)) * 16));
                cp16(smemBase + off, Qp + (long)r * Eq + c * 8);
            }
        }
        load_kv(0, 0);
        if (ntiles > 1) {
            load_kv(1, 64);
            asm volatile("cp.async.wait_group 1;" ::: "memory");
        } else {
            asm volatile("cp.async.wait_group 0;" ::: "memory");
        }
        __syncthreads();

        uint32_t qf[4][4];
        {
            int row = w * 16 + (lane & 7) + ((lane >> 3) & 1) * 8;
#pragma unroll
            for (int ks = 0; ks < 4; ks++) {
                int ch = ks * 2 + (lane >> 4);
                ldsm_x4(qf[ks], smemBase + (uint32_t)(row * 128
                         + ((ch ^ (row & 7)) * 16)));
            }
        }

        for (int kt = 0; kt < ntiles; kt++) {
            const int k0 = kt * 64;
            const uint32_t sK = smemBase + 8192 + (kt % NST) * 16384;
            const uint32_t sV = sK + 8192;

            float sf[8][4];
#pragma unroll
            for (int nj = 0; nj < 8; nj++) {
                sf[nj][0] = 0.f; sf[nj][1] = 0.f;
                sf[nj][2] = 0.f; sf[nj][3] = 0.f;
            }
#pragma unroll
            for (int ks = 0; ks < 4; ks++) {
#pragma unroll
                for (int nb = 0; nb < 4; nb++) {
                    int row = nb * 16 + (lane & 7) + ((lane >> 4) & 1) * 8;
                    int ch = ks * 2 + ((lane >> 3) & 1);
                    uint32_t bfr[4];
                    ldsm_x4(bfr, sK + (uint32_t)(row * 128
                             + ((ch ^ (row & 7)) * 16)));
                    mma_f16(sf[nb * 2],     qf[ks], bfr);
                    mma_f16(sf[nb * 2 + 1], qf[ks], bfr + 2);
                }
            }

            const bool needLen  = (k0 + 64 > len);
            const bool needDiag = causal && (k0 + 64 > q0);
            if (needLen || needDiag) {
#pragma unroll
                for (int nj = 0; nj < 8; nj++) {
                    int jg0 = k0 + nj * 8 + 2 * t, jg1 = jg0 + 1;
                    float a00 = (jg0 >= len ? NEGV : 0.f)
                              + (needDiag && jg0 > ig0 ? NEGV : 0.f);
                    float a01 = (jg1 >= len ? NEGV : 0.f)
                              + (needDiag && jg1 > ig0 ? NEGV : 0.f);
                    float a10 = (jg0 >= len ? NEGV : 0.f)
                              + (needDiag && jg0 > ig1 ? NEGV : 0.f);
                    float a11 = (jg1 >= len ? NEGV : 0.f)
                              + (needDiag && jg1 > ig1 ? NEGV : 0.f);
                    sf[nj][0] = (sf[nj][0] + a00) * SCALEV;
                    sf[nj][1] = (sf[nj][1] + a01) * SCALEV;
                    sf[nj][2] = (sf[nj][2] + a10) * SCALEV;
                    sf[nj][3] = (sf[nj][3] + a11) * SCALEV;
                }
            } else {
#pragma unroll
                for (int nj = 0; nj < 8; nj++) {
                    sf[nj][0] *= SCALEV; sf[nj][1] *= SCALEV;
                    sf[nj][2] *= SCALEV; sf[nj][3] *= SCALEV;
                }
            }

            float rm0 = -INFINITY, rm1 = -INFINITY;
#pragma unroll
            for (int nj = 0; nj < 8; nj++) {
                rm0 = fmaxf(rm0, fmaxf(sf[nj][0], sf[nj][1]));
                rm1 = fmaxf(rm1, fmaxf(sf[nj][2], sf[nj][3]));
            }
            rm0 = fmaxf(rm0, __shfl_xor_sync(0xffffffffu, rm0, 1));
            rm0 = fmaxf(rm0, __shfl_xor_sync(0xffffffffu, rm0, 2));
            rm1 = fmaxf(rm1, __shfl_xor_sync(0xffffffffu, rm1, 1));
            rm1 = fmaxf(rm1, __shfl_xor_sync(0xffffffffu, rm1, 2));

            float nm0 = fmaxf(m0, rm0), nm1 = fmaxf(m1, rm1);
            float al0 = __expf(m0 - nm0), al1 = __expf(m1 - nm1);
            m0 = nm0; m1 = nm1;

            float rs0 = 0.f, rs1 = 0.f;
#pragma unroll
            for (int nj = 0; nj < 8; nj++) {
                sf[nj][0] = __expf(sf[nj][0] - nm0);
                sf[nj][1] = __expf(sf[nj][1] - nm0);
                sf[nj][2] = __expf(sf[nj][2] - nm1);
                sf[nj][3] = __expf(sf[nj][3] - nm1);
                rs0 += sf[nj][0] + sf[nj][1];
                rs1 += sf[nj][2] + sf[nj][3];
            }
            rs0 += __shfl_xor_sync(0xffffffffu, rs0, 1);
            rs0 += __shfl_xor_sync(0xffffffffu, rs0, 2);
            rs1 += __shfl_xor_sync(0xffffffffu, rs1, 1);
            rs1 += __shfl_xor_sync(0xffffffffu, rs1, 2);
            l0 = l0 * al0 + rs0;
            l1 = l1 * al1 + rs1;

#pragma unroll
            for (int nd = 0; nd < 8; nd++) {
                of[nd][0] *= al0; of[nd][1] *= al0;
                of[nd][2] *= al1; of[nd][3] *= al1;
            }

#pragma unroll
            for (int kj = 0; kj < 4; kj++) {
                uint32_t pa[4];
                pa[0] = packh2(sf[2 * kj][0],     sf[2 * kj][1]);
                pa[1] = packh2(sf[2 * kj][2],     sf[2 * kj][3]);
                pa[2] = packh2(sf[2 * kj + 1][0], sf[2 * kj + 1][1]);
                pa[3] = packh2(sf[2 * kj + 1][2], sf[2 * kj + 1][3]);
                int row = kj * 16 + (lane & 7) + ((lane >> 3) & 1) * 8;
#pragma unroll
                for (int ndp = 0; ndp < 4; ndp++) {
                    int ch = ndp * 2 + (lane >> 4);
                    uint32_t vb[4];
                    ldsm_x4t(vb, sV + (uint32_t)(row * 128
                              + ((ch ^ (row & 7)) * 16)));
                    mma_f16(of[ndp * 2],     pa, vb);
                    mma_f16(of[ndp * 2 + 1], pa, vb + 2);
                }
            }

            if (kt + 2 < ntiles) {
                load_kv((kt + 2) % NST, (kt + 2) * 64);
                asm volatile("cp.async.wait_group 1;" ::: "memory");
            } else {
                asm volatile("cp.async.wait_group 0;" ::: "memory");
            }
            __syncthreads();
        }
    }

    const bool v0 = ig0 < len, v1 = ig1 < len;
    const float inv0 = v0 ? (1.f / l0) : 0.f;
    const float inv1 = v1 ? (1.f / l1) : 0.f;
    float* op = O + headBase;
#pragma unroll
    for (int nd = 0; nd < 8; nd++) {
        int c = nd * 8 + 2 * t;
        float2 r0v, r1v;
        r0v.x = of[nd][0] * inv0; r0v.y = of[nd][1] * inv0;
        r1v.x = of[nd][2] * inv1; r1v.y = of[nd][3] * inv1;
        *(float2*)(op + (long)ig0 * Eq + c) = r0v;
        *(float2*)(op + (long)ig1 * Eq + c) = r1v;
    }
}

// ------------ fused residual + layernorm (optional fp16 copy out) ------------
__global__ __launch_bounds__(256) void ln_kernel(
    const float* __restrict__ A, const float* __restrict__ Z,
    const float* __restrict__ g, const float* __restrict__ bb,
    float* __restrict__ out, __half* __restrict__ outh)
{
    __shared__ float sred[8], ssred[8];
    const int row = blockIdx.x, tid = threadIdx.x;
    const float4* a4 = (const float4*)(A + (long)row * Eq);
    const float4* z4 = (const float4*)(Z + (long)row * Eq);
    float4 av = a4[tid], zv = z4[tid];
    float4 t = make_float4(av.x+zv.x, av.y+zv.y, av.z+zv.z, av.w+zv.w);
    float s  = t.x + t.y + t.z + t.w;
    float ss = t.x*t.x + t.y*t.y + t.z*t.z + t.w*t.w;
#pragma unroll
    for (int o2 = 16; o2 > 0; o2 >>= 1) {
        s  += __shfl_xor_sync(0xffffffffu, s,  o2);
        ss += __shfl_xor_sync(0xffffffffu, ss, o2);
    }
    int wid = tid >> 5, lane = tid & 31;
    if (lane == 0) { sred[wid] = s; ssred[wid] = ss; }
    __syncthreads();
    if (tid < 8) {
        s = sred[tid]; ss = ssred[tid];
#pragma unroll
        for (int o2 = 4; o2 > 0; o2 >>= 1) {
            s  += __shfl_xor_sync(0xffu, s,  o2);
            ss += __shfl_xor_sync(0xffu, ss, o2);
        }
        if (tid == 0) { sred[0] = s; ssred[0] = ss; }
    }
    __syncthreads();
    const float mu  = sred[0] * (1.f / Eq);
    const float var = ssred[0] * (1.f / Eq) - mu * mu;
    const float rinv = rsqrtf(var + 1e-5f);
    float4 gv = ((const float4*)g)[tid];
    float4 bv = ((const float4*)bb)[tid];
    float4 r;
    r.x = (t.x - mu) * rinv * gv.x + bv.x;
    r.y = (t.y - mu) * rinv * gv.y + bv.y;
    r.z = (t.z - mu) * rinv * gv.z + bv.z;
    r.w = (t.w - mu) * rinv * gv.w + bv.w;
    ((float4*)(out + (long)row * Eq))[tid] = r;
    if (outh) {
        __half2* oh = (__half2*)(outh + (long)row * Eq);
        oh[tid * 2]     = __floats2half2_rn(r.x, r.y);
        oh[tid * 2 + 1] = __floats2half2_rn(r.z, r.w);
    }
}

// ---------------- launch ----------------
extern "C" void kernel_launch(void* const* d_in, const int* in_sizes, int n_in,
                              void* d_out, int out_size)
{
    const float* x    = (const float*)d_in[0];
    const float* ctx  = (const float*)d_in[1];
    const int*   lens = (const int*)  d_in[2];
    const float* Wq1  = (const float*)d_in[4];
    const float* Wk1  = (const float*)d_in[5];
    const float* Wv1  = (const float*)d_in[6];
    const float* Wq2  = (const float*)d_in[7];
    const float* Wk2  = (const float*)d_in[8];
    const float* Wv2  = (const float*)d_in[9];
    const float* ln1g = (const float*)d_in[10];
    const float* ln1b = (const float*)d_in[11];
    const float* ln2g = (const float*)d_in[12];
    const float* ln2b = (const float*)d_in[13];
    const float* ln3g = (const float*)d_in[14];
    const float* ln3b = (const float*)d_in[15];
    const float* fc1w = (const float*)d_in[16];
    const float* fc1b = (const float*)d_in[17];
    const float* fc2w = (const float*)d_in[18];
    const float* fc2b = (const float*)d_in[19];
    float* out = (float*)d_out;

    float *Zb, *X1, *X2;
    __half *Qh, *Kh, *Vh, *Q2h, *K2h, *xh, *ctxh, *X1h, *X2h, *Hbh, *Wt;
    cudaGetSymbolAddress((void**)&Zb, g_Z);
    cudaGetSymbolAddress((void**)&X1, g_X1);
    cudaGetSymbolAddress((void**)&X2, g_X2);
    cudaGetSymbolAddress((void**)&Qh,   g_Qh);
    cudaGetSymbolAddress((void**)&Kh,   g_Kh);
    cudaGetSymbolAddress((void**)&Vh,   g_Vh);
    cudaGetSymbolAddress((void**)&Q2h,  g_Q2h);
    cudaGetSymbolAddress((void**)&K2h,  g_K2h);
    cudaGetSymbolAddress((void**)&xh,   g_xh);
    cudaGetSymbolAddress((void**)&ctxh, g_ctxh);
    cudaGetSymbolAddress((void**)&X1h,  g_X1h);
    cudaGetSymbolAddress((void**)&X2h,  g_X2h);
    cudaGetSymbolAddress((void**)&Hbh,  g_Hbh);
    cudaGetSymbolAddress((void**)&Wt,   g_Wt);
#define WT(i) (Wt + (size_t)(i) * 1048576u)

    const int SMEM_G = NST * 32768;            // 96 KB gemm
    const int SMEM_F = 8192 + NST * 16384;     // 56 KB flash
    cudaFuncSetAttribute(gemm_h, cudaFuncAttributeMaxDynamicSharedMemorySize,
                         SMEM_G);
    cudaFuncSetAttribute(gemm_batch5, cudaFuncAttributeMaxDynamicSharedMemorySize,
                         SMEM_G);
    cudaFuncSetAttribute(flash_h, cudaFuncAttributeMaxDynamicSharedMemorySize,
                         SMEM_F);

    // --- prep: conversions + weight transposes (2 launches) ---
    {
        F2hArgs fa;
        fa.in[0] = x;   fa.out[0] = xh;
        fa.in[1] = ctx; fa.out[1] = ctxh;
        f2h_batch<<<dim3(Mq*Eq/1024, 2), 256>>>(fa);
    }
    {
        const long PSTRIDE = (long)Eq * DKq;
        WtrArgs wa;
        const float* ws[8] = {Wq1, Wk1, Wv1, Wq2, Wk2, Wv2, fc1w, fc2w};
        for (int i = 0; i < 8; i++) {
            wa.W[i] = ws[i];
            wa.ldb[i]     = (i < 6) ? DKq : Eq;
            wa.bstride[i] = (i < 6) ? PSTRIDE : 0L;
            wa.GRPs[i]    = (i < 6) ? 6 : 10;
        }
        wtr_batch<<<dim3(32, 32, 8), 256>>>(wa, Wt);
    }

    dim3 gg(Mq/128, Eq/128);         // 64 x 8
    dim3 fg(Lq/64, Bq*Hq);           // 16 x 128

    // --- all 5 context-independent projections in ONE launch ---
    {
        Gemm5Args ga;
        ga.A[0] = xh;   ga.W[0] = WT(0); ga.Ch[0] = Qh;
        ga.A[1] = xh;   ga.W[1] = WT(1); ga.Ch[1] = Kh;
        ga.A[2] = xh;   ga.W[2] = WT(2); ga.Ch[2] = Vh;
        ga.A[3] = ctxh; ga.W[3] = WT(3); ga.Ch[3] = Q2h;
        ga.A[4] = ctxh; ga.W[4] = WT(4); ga.Ch[4] = K2h;
        gemm_batch5<<<dim3(Mq/128, Eq/128, 5), 256, SMEM_G>>>(ga, lens);
    }

    // --- self attention ---
    flash_h<<<fg, 128, SMEM_F>>>(Qh, Kh, Vh, Zb, lens, 1);
    ln_kernel<<<Mq, 256>>>(x, Zb, ln1g, ln1b, X1, X1h);

    // --- cross attention (V from x1; Q,K precomputed from ctx) ---
    gemm_h<<<gg, 256, SMEM_G>>>(X1h, WT(5), nullptr, Vh, nullptr, lens, 0);
    flash_h<<<fg, 128, SMEM_F>>>(Q2h, K2h, Vh, Zb, lens, 0);
    ln_kernel<<<Mq, 256>>>(X1, Zb, ln2g, ln2b, X2, X2h);

    // --- FFN ---
    gemm_h<<<gg, 256, SMEM_G>>>(X2h, WT(6), nullptr, Hbh, fc1b, lens, 1);
    gemm_h<<<gg, 256, SMEM_G>>>(Hbh, WT(7), Zb, nullptr, fc2b, lens, 0);
    ln_kernel<<<Mq, 256>>>(X2, Zb, ln3g, ln3b, out, nullptr);
}